// round 12
// baseline (speedup 1.0000x reference)
#include <cuda_runtime.h>
#include <cuda_bf16.h>
#include <cuda_fp16.h>
#include <math.h>
#include <cstdint>

// ---------------- problem constants ----------------
#define NB     32
#define SEQ    197
#define SEQP   256
#define DMODEL 768
#define NHEAD  12
#define DHEAD  64
#define LAYERS 12
#define MLPD   3072
#define OUTD   1000
#define PPATCH 196
#define IN_DIM 768
#define NS     (NB * SEQ)       // 6304 tokens
#define NP     (NB * PPATCH)    // 6272 patches

// ---------------- device scratch ----------------
__device__ __half g_patches16[NP * IN_DIM];
__device__ float  g_tokens[NP * DMODEL];           // embed output; also logits scratch
__device__ float  g_x[NS * DMODEL];
__device__ __half g_h16[NS * DMODEL];
__device__ __half g_q16[NS * DMODEL];
__device__ __half g_k16[NS * DMODEL];
__device__ __half g_vT16[NB * NHEAD * 64 * SEQP];
__device__ __half g_mlp16[NS * MLPD];
__device__ __half g_wmapT16[DMODEL * IN_DIM];
__device__ __half g_w1T16[LAYERS * MLPD * DMODEL];
__device__ __half g_w2T16[LAYERS * DMODEL * MLPD];
__device__ __half g_wqT16[LAYERS * NHEAD * DHEAD * DHEAD];
__device__ __half g_wkT16[LAYERS * NHEAD * DHEAD * DHEAD];
__device__ __half g_wvT16[LAYERS * NHEAD * DHEAD * DHEAD];

__device__ __forceinline__ int il16(int c)
{
    int r = c & 15;
    int p = ((r & 7) >> 1) * 4 + ((r >> 3) << 1) + (r & 1);
    return (c & ~15) | p;
}
__device__ __forceinline__ int inv16(int c)
{
    int r = c & 15;
    int k = (((r & 3) < 2) ? 0 : 8) + ((r >> 2) << 1) + (r & 1);
    return (c & ~15) | k;
}

__device__ __forceinline__ void mma_f16(float* c, uint32_t a0, uint32_t a1,
                                        uint32_t a2, uint32_t a3,
                                        uint32_t b0, uint32_t b1)
{
    asm volatile(
        "mma.sync.aligned.m16n8k16.row.col.f32.f16.f16.f32 "
        "{%0,%1,%2,%3},{%4,%5,%6,%7},{%8,%9},{%0,%1,%2,%3};"
        : "+f"(c[0]), "+f"(c[1]), "+f"(c[2]), "+f"(c[3])
        : "r"(a0), "r"(a1), "r"(a2), "r"(a3), "r"(b0), "r"(b1));
}

// ---------------- weight prep ----------------
__global__ void __launch_bounds__(256)
cvtT16_kernel(const float* __restrict__ src, __half* __restrict__ dst, int R, int C)
{
    __shared__ float t[32][33];
    size_t zoff = (size_t)blockIdx.z * R * C;
    int bx = blockIdx.x * 32;
    int by = blockIdx.y * 32;
    int tx = threadIdx.x & 31;
    int ty = threadIdx.x >> 5;
    #pragma unroll
    for (int i = 0; i < 32; i += 8)
        t[ty + i][tx] = src[zoff + (size_t)(by + ty + i) * C + bx + tx];
    __syncthreads();
    int kp = il16(by + tx);
    #pragma unroll
    for (int i = 0; i < 32; i += 8)
        dst[zoff + (size_t)(bx + ty + i) * R + kp] = __float2half(t[tx][ty + i]);
}

// ---------------- patchify ----------------
__global__ void __launch_bounds__(256)
patchify_kernel(const float* __restrict__ img)
{
    int idx = blockIdx.x * 256 + threadIdx.x;
    if (idx >= NP * IN_DIM) return;
    int t = idx / IN_DIM;
    int ep = idx - t * IN_DIM;
    int e = inv16(ep);
    int n = t / PPATCH;
    int p = t - n * PPATCH;
    int py = p / 14, px = p - py * 14;
    int c  = e >> 8;
    int r  = e & 255;
    int ph = r >> 4, pw = r & 15;
    g_patches16[idx] = __float2half(
        img[(((size_t)n * 3 + c) * 224 + (py * 16 + ph)) * 224 + px * 16 + pw]);
}

// ---------------- assemble ----------------
__global__ void __launch_bounds__(256)
assemble_kernel(const float* __restrict__ tokens, const float* __restrict__ cls,
                const float* __restrict__ pos)
{
    int idx = blockIdx.x * 256 + threadIdx.x;
    if (idx >= NS * DMODEL) return;
    int t = idx / DMODEL;
    int d = idx - t * DMODEL;
    int n = t / SEQ;
    int s = t - n * SEQ;
    float v = (s == 0) ? cls[d] : tokens[((size_t)(n * PPATCH + s - 1)) * DMODEL + d];
    g_x[idx] = v + pos[s * DMODEL + d];
}

// ---------------- fp16 tensor-core GEMM (3 CTAs/SM) ----------
#define TG16_STAGE 24576
#define TG16_SMEM  (3 * TG16_STAGE)   // 73728 bytes

template<int EPI>
__global__ void __launch_bounds__(128, 3)
tgemm16(const __half* __restrict__ A, const __half* __restrict__ Bt,
        const float* __restrict__ bias, const float* __restrict__ res,
        void* __restrict__ Cv, int M, int N, int K)
{
    extern __shared__ char sm16[];

    const int tid  = threadIdx.x;
    const int wid  = tid >> 5;
    const int lane = tid & 31;
    const int g    = lane >> 2;
    const int tig  = lane & 3;
    const int mw   = wid & 1;
    const int nw   = wid >> 1;
    const int bm   = blockIdx.y * 128;
    const int bn   = blockIdx.x * 128;

    float acc[4][8][4];
    #pragma unroll
    for (int i = 0; i < 4; i++)
        #pragma unroll
        for (int j = 0; j < 8; j++)
            #pragma unroll
            for (int c = 0; c < 4; c++) acc[i][j][c] = 0.f;

    auto As = [&](int buf) { return (__half*)(sm16 + buf * TG16_STAGE); };
    auto Bs = [&](int buf) { return (__half*)(sm16 + buf * TG16_STAGE + 12288); };

    auto load_tile = [&](int kt, int buf) {
        __half* as = As(buf);
        __half* bs = Bs(buf);
        const int kk0 = kt * 32;
        #pragma unroll
        for (int p = 0; p < 4; p++) {
            int idx = p * 128 + tid;
            int row = idx >> 2;
            int ch  = idx & 3;
            const __half* src = A + (size_t)(bm + row) * K + kk0 + ch * 8;
            uint32_t dst = (uint32_t)__cvta_generic_to_shared(as + row * 48 + ch * 8);
            int sz = (bm + row) < M ? 16 : 0;
            asm volatile("cp.async.cg.shared.global [%0], [%1], 16, %2;"
                         :: "r"(dst), "l"(src), "r"(sz) : "memory");
        }
        #pragma unroll
        for (int p = 0; p < 4; p++) {
            int idx = p * 128 + tid;
            int row = idx >> 2;
            int ch  = idx & 3;
            const __half* src = Bt + (size_t)(bn + row) * K + kk0 + ch * 8;
            uint32_t dst = (uint32_t)__cvta_generic_to_shared(bs + row * 48 + ch * 8);
            asm volatile("cp.async.cg.shared.global [%0], [%1], 16;"
                         :: "r"(dst), "l"(src) : "memory");
        }
        asm volatile("cp.async.commit_group;" ::: "memory");
    };

    const int T = K >> 5;
    load_tile(0, 0);
    if (T > 1) load_tile(1, 1);

    int buf = 0;
    for (int kt = 0; kt < T; kt++) {
        if (kt + 1 < T) asm volatile("cp.async.wait_group 1;" ::: "memory");
        else            asm volatile("cp.async.wait_group 0;" ::: "memory");
        __syncthreads();

        if (kt + 2 < T) load_tile(kt + 2, (kt + 2) % 3);

        const __half* as = As(buf);
        const __half* bs = Bs(buf);

        #pragma unroll
        for (int s = 0; s < 2; s++) {
            uint32_t af[4][4];
            #pragma unroll
            for (int mt = 0; mt < 4; mt++) {
                int rb = mw * 64 + mt * 16;
                uint2 lo = *(const uint2*)(as + (rb + g)     * 48 + s * 16 + tig * 4);
                uint2 hi = *(const uint2*)(as + (rb + g + 8) * 48 + s * 16 + tig * 4);
                af[mt][0] = lo.x; af[mt][1] = hi.x; af[mt][2] = lo.y; af[mt][3] = hi.y;
            }
            #pragma unroll
            for (int nt = 0; nt < 8; nt++) {
                int cb = nw * 64 + nt * 8;
                uint2 bv = *(const uint2*)(bs + (cb + g) * 48 + s * 16 + tig * 4);
                #pragma unroll
                for (int mt = 0; mt < 4; mt++)
                    mma_f16(acc[mt][nt], af[mt][0], af[mt][1], af[mt][2], af[mt][3],
                            bv.x, bv.y);
            }
        }
        buf = (buf == 2) ? 0 : buf + 1;
    }

    float* Cf = (float*)Cv;
    __half* Ch = (__half*)Cv;
    #pragma unroll
    for (int mt = 0; mt < 4; mt++) {
        int r0 = bm + mw * 64 + mt * 16 + g;
        #pragma unroll
        for (int nt = 0; nt < 8; nt++) {
            int c0 = bn + nw * 64 + nt * 8 + 2 * tig;
            float b0 = bias[c0], b1 = bias[c0 + 1];
            #pragma unroll
            for (int h = 0; h < 2; h++) {
                int row = r0 + h * 8;
                if (row >= M) continue;
                float v0 = acc[mt][nt][h * 2 + 0] + b0;
                float v1 = acc[mt][nt][h * 2 + 1] + b1;
                if (EPI == 1) {
                    v0 = 0.5f * v0 * (1.f + erff(v0 * 0.70710678118654752f));
                    v1 = 0.5f * v1 * (1.f + erff(v1 * 0.70710678118654752f));
                    int pos = il16(c0);
                    __half2 hv = __floats2half2_rn(v0, v1);
                    *(__half2*)(Ch + (size_t)row * N + pos) = hv;
                } else {
                    if (EPI == 2) {
                        const float2 rr = *(const float2*)(res + (size_t)row * N + c0);
                        v0 += rr.x; v1 += rr.y;
                    }
                    float2 o; o.x = v0; o.y = v1;
                    *(float2*)(Cf + (size_t)row * N + c0) = o;
                }
            }
        }
    }
}

// ---------------- LayerNorm: fp16 interleaved out ----------------
__global__ void __launch_bounds__(256)
ln_h_kernel(const float* __restrict__ x, const float* __restrict__ g,
            const float* __restrict__ b, __half* __restrict__ o)
{
    int row = blockIdx.x;
    int tid = threadIdx.x;
    const float* xr = x + (size_t)row * DMODEL;
    float v0 = xr[tid], v1 = xr[tid + 256], v2 = xr[tid + 512];

    __shared__ float red[10];
    float s = v0 + v1 + v2;
    #pragma unroll
    for (int of = 16; of; of >>= 1) s += __shfl_xor_sync(~0u, s, of);
    if ((tid & 31) == 0) red[tid >> 5] = s;
    __syncthreads();
    if (tid == 0) {
        float t = 0.f;
        #pragma unroll
        for (int i = 0; i < 8; i++) t += red[i];
        red[8] = t * (1.f / 768.f);
    }
    __syncthreads();
    float mu = red[8];
    float d0 = v0 - mu, d1 = v1 - mu, d2 = v2 - mu;
    float q = d0 * d0 + d1 * d1 + d2 * d2;
    #pragma unroll
    for (int of = 16; of; of >>= 1) q += __shfl_xor_sync(~0u, q, of);
    if ((tid & 31) == 0) red[tid >> 5] = q;
    __syncthreads();
    if (tid == 0) {
        float t = 0.f;
        #pragma unroll
        for (int i = 0; i < 8; i++) t += red[i];
        red[9] = rsqrtf(t * (1.f / 768.f) + 1e-5f);
    }
    __syncthreads();
    float inv = red[9];
    __half* orow = o + (size_t)row * DMODEL;
    orow[il16(tid)]       = __float2half(d0 * inv * g[tid]       + b[tid]);
    orow[il16(tid + 256)] = __float2half(d1 * inv * g[tid + 256] + b[tid + 256]);
    orow[il16(tid + 512)] = __float2half(d2 * inv * g[tid + 512] + b[tid + 512]);
}

// ---------------- per-head QKV projection, fp16 mma ----------------
__global__ void __launch_bounds__(128)
qkv16_kernel(const __half* __restrict__ h,
             const __half* __restrict__ Wq, const __half* __restrict__ Wk,
             const __half* __restrict__ Wv,
             const float* __restrict__ bq, const float* __restrict__ bk,
             const float* __restrict__ bv,
             __half* __restrict__ q, __half* __restrict__ k, __half* __restrict__ vT)
{
    __shared__ __half Xs[64][80];
    __shared__ __half Ws[64][80];

    const int t0 = blockIdx.x * 64;
    const int hh = blockIdx.y;
    const int z  = blockIdx.z;
    const __half* W = ((z == 0) ? Wq : (z == 1) ? Wk : Wv) + hh * 64 * 64;
    const float* bb = ((z == 0) ? bq : (z == 1) ? bk : bv) + hh * 64;

    const int tid  = threadIdx.x;
    const int wid  = tid >> 5;
    const int lane = tid & 31;
    const int g    = lane >> 2;
    const int tig  = lane & 3;
    const int rb   = wid * 16;

    #pragma unroll
    for (int it = 0; it < 4; it++) {
        int idx = it * 128 + tid;
        int row = idx >> 3;
        int ch  = idx & 7;
        int tok = t0 + row;
        uint4 xv = make_uint4(0u, 0u, 0u, 0u);
        if (tok < NS) xv = *(const uint4*)(h + (size_t)tok * DMODEL + hh * 64 + ch * 8);
        *(uint4*)&Xs[row][ch * 8] = xv;
        *(uint4*)&Ws[row][ch * 8] = *(const uint4*)(W + row * 64 + ch * 8);
    }
    __syncthreads();

    float acc[8][4];
    #pragma unroll
    for (int nt = 0; nt < 8; nt++)
        #pragma unroll
        for (int c = 0; c < 4; c++) acc[nt][c] = 0.f;

    #pragma unroll
    for (int s = 0; s < 4; s++) {
        uint2 lo = *(const uint2*)&Xs[rb + g]    [s * 16 + tig * 4];
        uint2 hi = *(const uint2*)&Xs[rb + g + 8][s * 16 + tig * 4];
        #pragma unroll
        for (int nt = 0; nt < 8; nt++) {
            uint2 bv = *(const uint2*)&Ws[nt * 8 + g][s * 16 + tig * 4];
            mma_f16(acc[nt], lo.x, hi.x, lo.y, hi.y, bv.x, bv.y);
        }
    }

    __half* out = (z == 0) ? q : k;
    #pragma unroll
    for (int nt = 0; nt < 8; nt++) {
        int c0 = nt * 8 + 2 * tig;
        float b0 = bb[c0], b1 = bb[c0 + 1];
        #pragma unroll
        for (int hlf = 0; hlf < 2; hlf++) {
            int tok = t0 + rb + g + hlf * 8;
            if (tok >= NS) continue;
            float v0 = acc[nt][hlf * 2 + 0] + b0;
            float v1 = acc[nt][hlf * 2 + 1] + b1;
            if (z < 2) {
                __half2 hv = __floats2half2_rn(v0, v1);
                *(__half2*)(out + (size_t)tok * DMODEL + hh * 64 + il16(c0)) = hv;
            } else {
                int n  = tok / SEQ;
                int s_ = tok - n * SEQ;
                int b  = n * NHEAD + hh;
                int kp = il16(s_);
                vT[((size_t)b * 64 + c0)     * SEQP + kp] = __float2half(v0);
                vT[((size_t)b * 64 + c0 + 1) * SEQP + kp] = __float2half(v1);
            }
        }
    }
}

// ---------------- fused flash attention, fp16 mma ----------------
__global__ void __launch_bounds__(128)
attn16_kernel(const __half* __restrict__ q, const __half* __restrict__ k,
              const __half* __restrict__ vT, float* __restrict__ x)
{
    __shared__ __half Qs[64][80];
    __shared__ __half Ks[64][80];
    __shared__ __half Ps[64][80];
    __shared__ __half Vs[64][80];

    const int q0 = blockIdx.x * 64;
    const int b  = blockIdx.y;
    const int n  = b / NHEAD, hh = b - n * NHEAD;
    const int tid  = threadIdx.x;
    const int wid  = tid >> 5;
    const int lane = tid & 31;
    const int g    = lane >> 2;
    const int tig  = lane & 3;
    const int rb   = wid * 16;

    #pragma unroll
    for (int it = 0; it < 4; it++) {
        int idx = it * 128 + tid;
        int row = idx >> 3;
        int ch  = idx & 7;
        int qt = q0 + row;
        uint4 qv = make_uint4(0u, 0u, 0u, 0u);
        if (qt < SEQ) qv = *(const uint4*)(q + (size_t)(n * SEQ + qt) * DMODEL + hh * 64 + ch * 8);
        *(uint4*)&Qs[row][ch * 8] = qv;
    }

    float m_run[2] = {-1e30f, -1e30f};
    float l_run[2] = {0.f, 0.f};
    float acc_o[8][4];
    #pragma unroll
    for (int nt = 0; nt < 8; nt++)
        #pragma unroll
        for (int c = 0; c < 4; c++) acc_o[nt][c] = 0.f;

    for (int kt = 0; kt < 4; kt++) {
        const int k0 = kt * 64;
        __syncthreads();

        #pragma unroll
        for (int it = 0; it < 4; it++) {
            int idx = it * 128 + tid;
            int row = idx >> 3;
            int ch  = idx & 7;
            int ktok = k0 + row;
            uint4 kv = make_uint4(0u, 0u, 0u, 0u);
            if (ktok < SEQ)
                kv = *(const uint4*)(k + (size_t)(n * SEQ + ktok) * DMODEL + hh * 64 + ch * 8);
            *(uint4*)&Ks[row][ch * 8] = kv;
            *(uint4*)&Vs[row][ch * 8] =
                *(const uint4*)(vT + ((size_t)b * 64 + row) * SEQP + k0 + ch * 8);
        }
        __syncthreads();

        float s[8][4];
        #pragma unroll
        for (int nt = 0; nt < 8; nt++)
            #pragma unroll
            for (int c = 0; c < 4; c++) s[nt][c] = 0.f;

        #pragma unroll
        for (int ss = 0; ss < 4; ss++) {
            uint2 lo = *(const uint2*)&Qs[rb + g]    [ss * 16 + tig * 4];
            uint2 hi = *(const uint2*)&Qs[rb + g + 8][ss * 16 + tig * 4];
            #pragma unroll
            for (int nt = 0; nt < 8; nt++) {
                uint2 bv = *(const uint2*)&Ks[nt * 8 + g][ss * 16 + tig * 4];
                mma_f16(s[nt], lo.x, hi.x, lo.y, hi.y, bv.x, bv.y);
            }
        }

        #pragma unroll
        for (int nt = 0; nt < 8; nt++) {
            int c0 = k0 + nt * 8 + 2 * tig;
            s[nt][0] = (c0     < SEQ) ? s[nt][0] * 0.125f : -1e30f;
            s[nt][1] = (c0 + 1 < SEQ) ? s[nt][1] * 0.125f : -1e30f;
            s[nt][2] = (c0     < SEQ) ? s[nt][2] * 0.125f : -1e30f;
            s[nt][3] = (c0 + 1 < SEQ) ? s[nt][3] * 0.125f : -1e30f;
        }

        #pragma unroll
        for (int r = 0; r < 2; r++) {
            float mt_ = -1e30f;
            #pragma unroll
            for (int nt = 0; nt < 8; nt++)
                mt_ = fmaxf(mt_, fmaxf(s[nt][2 * r], s[nt][2 * r + 1]));
            mt_ = fmaxf(mt_, __shfl_xor_sync(~0u, mt_, 1));
            mt_ = fmaxf(mt_, __shfl_xor_sync(~0u, mt_, 2));
            float mnew = fmaxf(m_run[r], mt_);
            float sc = expf(m_run[r] - mnew);
            float rs = 0.f;
            #pragma unroll
            for (int nt = 0; nt < 8; nt++) {
                float p0 = expf(s[nt][2 * r]     - mnew);
                float p1 = expf(s[nt][2 * r + 1] - mnew);
                s[nt][2 * r] = p0; s[nt][2 * r + 1] = p1;
                rs += p0 + p1;
            }
            rs += __shfl_xor_sync(~0u, rs, 1);
            rs += __shfl_xor_sync(~0u, rs, 2);
            l_run[r] = l_run[r] * sc + rs;
            #pragma unroll
            for (int nt = 0; nt < 8; nt++) {
                acc_o[nt][2 * r]     *= sc;
                acc_o[nt][2 * r + 1] *= sc;
            }
            m_run[r] = mnew;
        }

        #pragma unroll
        for (int nt = 0; nt < 8; nt++) {
            int pc = il16(nt * 8 + 2 * tig);
            *(__half2*)&Ps[rb + g]    [pc] = __floats2half2_rn(s[nt][0], s[nt][1]);
            *(__half2*)&Ps[rb + g + 8][pc] = __floats2half2_rn(s[nt][2], s[nt][3]);
        }
        __syncwarp();

        #pragma unroll
        for (int ss = 0; ss < 4; ss++) {
            uint2 lo = *(const uint2*)&Ps[rb + g]    [ss * 16 + tig * 4];
            uint2 hi = *(const uint2*)&Ps[rb + g + 8][ss * 16 + tig * 4];
            #pragma unroll
            for (int nt = 0; nt < 8; nt++) {
                uint2 bv = *(const uint2*)&Vs[nt * 8 + g][ss * 16 + tig * 4];
                mma_f16(acc_o[nt], lo.x, hi.x, lo.y, hi.y, bv.x, bv.y);
            }
        }
    }

    #pragma unroll
    for (int r = 0; r < 2; r++) {
        int row = q0 + rb + g + r * 8;
        if (row >= SEQ) continue;
        float inv = 1.f / l_run[r];
        #pragma unroll
        for (int nt = 0; nt < 8; nt++) {
            int col = hh * 64 + nt * 8 + 2 * tig;
            float* px = x + (size_t)(n * SEQ + row) * DMODEL + col;
            float2 old = *(float2*)px;
            old.x += acc_o[nt][2 * r]     * inv;
            old.y += acc_o[nt][2 * r + 1] * inv;
            *(float2*)px = old;
        }
    }
}

// ---------------- head: parallel logits ----------------
__global__ void __launch_bounds__(256)
logits_kernel(const float* __restrict__ x, const float* __restrict__ Wh,
              const float* __restrict__ bh, float* __restrict__ lg)
{
    __shared__ float xs[DMODEL];
    int n  = blockIdx.y;
    int o  = blockIdx.x * 256 + threadIdx.x;
    for (int i = threadIdx.x; i < DMODEL; i += 256)
        xs[i] = x[(size_t)n * SEQ * DMODEL + i];
    __syncthreads();
    if (o >= OUTD) return;
    float a = bh[o];
    #pragma unroll 4
    for (int kk = 0; kk < DMODEL; kk++)
        a = fmaf(xs[kk], Wh[(size_t)kk * OUTD + o], a);
    lg[n * OUTD + o] = a;
}

// ---------------- head: per-image softmax ----------------
__global__ void __launch_bounds__(256)
head_softmax_kernel(const float* __restrict__ lg, float* __restrict__ out)
{
    __shared__ float red[256];
    int n = blockIdx.x, tid = threadIdx.x;
    const float* l = lg + n * OUTD;
    float m = -1e30f;
    for (int o = tid; o < OUTD; o += 256) m = fmaxf(m, l[o]);
    red[tid] = m; __syncthreads();
    for (int s = 128; s; s >>= 1) { if (tid < s) red[tid] = fmaxf(red[tid], red[tid + s]); __syncthreads(); }
    float mx = red[0]; __syncthreads();
    float sm = 0.f;
    for (int o = tid; o < OUTD; o += 256) sm += expf(l[o] - mx);
    red[tid] = sm; __syncthreads();
    for (int s = 128; s; s >>= 1) { if (tid < s) red[tid] += red[tid + s]; __syncthreads(); }
    float inv = 1.f / red[0];
    __syncthreads();
    for (int o = tid; o < OUTD; o += 256)
        out[(size_t)n * OUTD + o] = expf(l[o] - mx) * inv;
}

// ---------------- host orchestration ----------------
extern "C" void kernel_launch(void* const* d_in, const int* in_sizes, int n_in,
                              void* d_out, int out_size)
{
    const float* images   = (const float*)d_in[0];
    const float* W_map    = (const float*)d_in[1];
    const float* b_map    = (const float*)d_in[2];
    const float* cls      = (const float*)d_in[3];
    const float* pos      = (const float*)d_in[4];
    const float* ln1_g    = (const float*)d_in[5];
    const float* ln1_b    = (const float*)d_in[6];
    const float* Wq       = (const float*)d_in[7];
    const float* bq       = (const float*)d_in[8];
    const float* Wk       = (const float*)d_in[9];
    const float* bk       = (const float*)d_in[10];
    const float* Wv       = (const float*)d_in[11];
    const float* bv       = (const float*)d_in[12];
    const float* ln2_g    = (const float*)d_in[13];
    const float* ln2_b    = (const float*)d_in[14];
    const float* W1       = (const float*)d_in[15];
    const float* b1       = (const float*)d_in[16];
    const float* W2       = (const float*)d_in[17];
    const float* b2       = (const float*)d_in[18];
    const float* W_head   = (const float*)d_in[19];
    const float* b_head   = (const float*)d_in[20];
    float* out = (float*)d_out;

    __half *p_patches16, *p_h16, *p_mlp16, *p_q16, *p_k16, *p_vT16;
    __half *p_wmapT16, *p_w1T16, *p_w2T16, *p_wqT16, *p_wkT16, *p_wvT16;
    float *p_tokens, *p_x;
    cudaGetSymbolAddress((void**)&p_patches16, g_patches16);
    cudaGetSymbolAddress((void**)&p_tokens, g_tokens);
    cudaGetSymbolAddress((void**)&p_x, g_x);
    cudaGetSymbolAddress((void**)&p_h16, g_h16);
    cudaGetSymbolAddress((void**)&p_q16, g_q16);
    cudaGetSymbolAddress((void**)&p_k16, g_k16);
    cudaGetSymbolAddress((void**)&p_vT16, g_vT16);
    cudaGetSymbolAddress((void**)&p_mlp16, g_mlp16);
    cudaGetSymbolAddress((void**)&p_wmapT16, g_wmapT16);
    cudaGetSymbolAddress((void**)&p_w1T16, g_w1T16);
    cudaGetSymbolAddress((void**)&p_w2T16, g_w2T16);
    cudaGetSymbolAddress((void**)&p_wqT16, g_wqT16);
    cudaGetSymbolAddress((void**)&p_wkT16, g_wkT16);
    cudaGetSymbolAddress((void**)&p_wvT16, g_wvT16);

    cudaFuncSetAttribute(tgemm16<0>, cudaFuncAttributeMaxDynamicSharedMemorySize, TG16_SMEM);
    cudaFuncSetAttribute(tgemm16<1>, cudaFuncAttributeMaxDynamicSharedMemorySize, TG16_SMEM);
    cudaFuncSetAttribute(tgemm16<2>, cudaFuncAttributeMaxDynamicSharedMemorySize, TG16_SMEM);

    // 0) weight prep
    {
        dim3 gmap(DMODEL / 32, IN_DIM / 32, 1);
        cvtT16_kernel<<<gmap, 256>>>(W_map, p_wmapT16, IN_DIM, DMODEL);
        dim3 g1(MLPD / 32, DMODEL / 32, LAYERS);
        cvtT16_kernel<<<g1, 256>>>(W1, p_w1T16, DMODEL, MLPD);
        dim3 g2(DMODEL / 32, MLPD / 32, LAYERS);
        cvtT16_kernel<<<g2, 256>>>(W2, p_w2T16, MLPD, DMODEL);
        dim3 gq(2, 2, LAYERS * NHEAD);
        cvtT16_kernel<<<gq, 256>>>(Wq, p_wqT16, DHEAD, DHEAD);
        cvtT16_kernel<<<gq, 256>>>(Wk, p_wkT16, DHEAD, DHEAD);
        cvtT16_kernel<<<gq, 256>>>(Wv, p_wvT16, DHEAD, DHEAD);
    }

    // 1) patchify + embed + assemble
    patchify_kernel<<<(NP * IN_DIM) / 256, 256>>>(images);
    {
        dim3 grid(DMODEL / 128, NP / 128);
        tgemm16<0><<<grid, 128, TG16_SMEM>>>(p_patches16, p_wmapT16, b_map, nullptr,
                                             p_tokens, NP, DMODEL, IN_DIM);
    }
    assemble_kernel<<<(NS * DMODEL) / 256, 256>>>(p_tokens, cls, pos);

    // 2) transformer blocks
    for (int l = 0; l < LAYERS; l++) {
        ln_h_kernel<<<NS, 256>>>(p_x, ln1_g + l * DMODEL, ln1_b + l * DMODEL, p_h16);

        {
            dim3 grid((NS + 63) / 64, NHEAD, 3);
            qkv16_kernel<<<grid, 128>>>(p_h16,
                p_wqT16 + (size_t)l * NHEAD * DHEAD * DHEAD,
                p_wkT16 + (size_t)l * NHEAD * DHEAD * DHEAD,
                p_wvT16 + (size_t)l * NHEAD * DHEAD * DHEAD,
                bq + (size_t)l * NHEAD * DHEAD,
                bk + (size_t)l * NHEAD * DHEAD,
                bv + (size_t)l * NHEAD * DHEAD,
                p_q16, p_k16, p_vT16);
        }
        {
            dim3 grid((SEQ + 63) / 64, NB * NHEAD);
            attn16_kernel<<<grid, 128>>>(p_q16, p_k16, p_vT16, p_x);
        }

        ln_h_kernel<<<NS, 256>>>(p_x, ln2_g + l * DMODEL, ln2_b + l * DMODEL, p_h16);
        {
            dim3 grid(MLPD / 128, (NS + 127) / 128);
            tgemm16<1><<<grid, 128, TG16_SMEM>>>(p_h16, p_w1T16 + (size_t)l * DMODEL * MLPD,
                                                 b1 + (size_t)l * MLPD, nullptr,
                                                 p_mlp16, NS, MLPD, DMODEL);
        }
        {
            dim3 grid(DMODEL / 128, (NS + 127) / 128);
            tgemm16<2><<<grid, 128, TG16_SMEM>>>(p_mlp16, p_w2T16 + (size_t)l * MLPD * DMODEL,
                                                 b2 + (size_t)l * DMODEL, p_x,
                                                 p_x, NS, DMODEL, MLPD);
        }
    }

    // 3) head: logits (parallel) + softmax
    {
        dim3 grid((OUTD + 255) / 256, NB);
        logits_kernel<<<grid, 256>>>(p_x, W_head, b_head, p_tokens);
    }
    head_softmax_kernel<<<NB, 256>>>(p_tokens, out);
}

// round 13
// speedup vs baseline: 1.1398x; 1.1398x over previous
#include <cuda_runtime.h>
#include <cuda_bf16.h>
#include <cuda_fp16.h>
#include <math.h>
#include <cstdint>

// ---------------- problem constants ----------------
#define NB     32
#define SEQ    197
#define SEQP   256
#define DMODEL 768
#define NHEAD  12
#define DHEAD  64
#define LAYERS 12
#define MLPD   3072
#define OUTD   1000
#define PPATCH 196
#define IN_DIM 768
#define NS     (NB * SEQ)       // 6304 tokens
#define NP     (NB * PPATCH)    // 6272 patches

// ---------------- device scratch ----------------
__device__ __half g_patches16[NP * IN_DIM];
__device__ float  g_tokens[NP * DMODEL];           // embed output; also logits scratch
__device__ float  g_x[NS * DMODEL];
__device__ __half g_h16[NS * DMODEL];
__device__ __half g_q16[NS * DMODEL];
__device__ __half g_k16[NS * DMODEL];
__device__ __half g_vT16[NB * NHEAD * 64 * SEQP];
__device__ __half g_mlp16[NS * MLPD];
__device__ __half g_wmapT16[DMODEL * IN_DIM];
__device__ __half g_w1T16[LAYERS * MLPD * DMODEL];
__device__ __half g_w2T16[LAYERS * DMODEL * MLPD];
__device__ __half g_wqT16[LAYERS * NHEAD * DHEAD * DHEAD];
__device__ __half g_wkT16[LAYERS * NHEAD * DHEAD * DHEAD];
__device__ __half g_wvT16[LAYERS * NHEAD * DHEAD * DHEAD];

__device__ __forceinline__ int il16(int c)
{
    int r = c & 15;
    int p = ((r & 7) >> 1) * 4 + ((r >> 3) << 1) + (r & 1);
    return (c & ~15) | p;
}
__device__ __forceinline__ int inv16(int c)
{
    int r = c & 15;
    int k = (((r & 3) < 2) ? 0 : 8) + ((r >> 2) << 1) + (r & 1);
    return (c & ~15) | k;
}

__device__ __forceinline__ void mma_f16(float* c, uint32_t a0, uint32_t a1,
                                        uint32_t a2, uint32_t a3,
                                        uint32_t b0, uint32_t b1)
{
    asm volatile(
        "mma.sync.aligned.m16n8k16.row.col.f32.f16.f16.f32 "
        "{%0,%1,%2,%3},{%4,%5,%6,%7},{%8,%9},{%0,%1,%2,%3};"
        : "+f"(c[0]), "+f"(c[1]), "+f"(c[2]), "+f"(c[3])
        : "r"(a0), "r"(a1), "r"(a2), "r"(a3), "r"(b0), "r"(b1));
}

// ---------------- weight prep ----------------
__global__ void __launch_bounds__(256)
cvtT16_kernel(const float* __restrict__ src, __half* __restrict__ dst, int R, int C)
{
    __shared__ float t[32][33];
    size_t zoff = (size_t)blockIdx.z * R * C;
    int bx = blockIdx.x * 32;
    int by = blockIdx.y * 32;
    int tx = threadIdx.x & 31;
    int ty = threadIdx.x >> 5;
    #pragma unroll
    for (int i = 0; i < 32; i += 8)
        t[ty + i][tx] = src[zoff + (size_t)(by + ty + i) * C + bx + tx];
    __syncthreads();
    int kp = il16(by + tx);
    #pragma unroll
    for (int i = 0; i < 32; i += 8)
        dst[zoff + (size_t)(bx + ty + i) * R + kp] = __float2half(t[tx][ty + i]);
}

// ---------------- patchify ----------------
__global__ void __launch_bounds__(256)
patchify_kernel(const float* __restrict__ img)
{
    int idx = blockIdx.x * 256 + threadIdx.x;
    if (idx >= NP * IN_DIM) return;
    int t = idx / IN_DIM;
    int ep = idx - t * IN_DIM;
    int e = inv16(ep);
    int n = t / PPATCH;
    int p = t - n * PPATCH;
    int py = p / 14, px = p - py * 14;
    int c  = e >> 8;
    int r  = e & 255;
    int ph = r >> 4, pw = r & 15;
    g_patches16[idx] = __float2half(
        img[(((size_t)n * 3 + c) * 224 + (py * 16 + ph)) * 224 + px * 16 + pw]);
}

// ---------------- assemble ----------------
__global__ void __launch_bounds__(256)
assemble_kernel(const float* __restrict__ tokens, const float* __restrict__ cls,
                const float* __restrict__ pos)
{
    int idx = blockIdx.x * 256 + threadIdx.x;
    if (idx >= NS * DMODEL) return;
    int t = idx / DMODEL;
    int d = idx - t * DMODEL;
    int n = t / SEQ;
    int s = t - n * SEQ;
    float v = (s == 0) ? cls[d] : tokens[((size_t)(n * PPATCH + s - 1)) * DMODEL + d];
    g_x[idx] = v + pos[s * DMODEL + d];
}

// ---------------- fp16 tensor-core GEMM (proven R11 config: 2 CTAs/SM) ----------
#define TG16_STAGE 24576
#define TG16_SMEM  (3 * TG16_STAGE)   // 73728 bytes

template<int EPI>
__global__ void __launch_bounds__(128, 2)
tgemm16(const __half* __restrict__ A, const __half* __restrict__ Bt,
        const float* __restrict__ bias, const float* __restrict__ res,
        void* __restrict__ Cv, int M, int N, int K)
{
    extern __shared__ char sm16[];

    const int tid  = threadIdx.x;
    const int wid  = tid >> 5;
    const int lane = tid & 31;
    const int g    = lane >> 2;
    const int tig  = lane & 3;
    const int mw   = wid & 1;
    const int nw   = wid >> 1;
    const int bm   = blockIdx.y * 128;
    const int bn   = blockIdx.x * 128;

    float acc[4][8][4];
    #pragma unroll
    for (int i = 0; i < 4; i++)
        #pragma unroll
        for (int j = 0; j < 8; j++)
            #pragma unroll
            for (int c = 0; c < 4; c++) acc[i][j][c] = 0.f;

    auto As = [&](int buf) { return (__half*)(sm16 + buf * TG16_STAGE); };
    auto Bs = [&](int buf) { return (__half*)(sm16 + buf * TG16_STAGE + 12288); };

    auto load_tile = [&](int kt, int buf) {
        __half* as = As(buf);
        __half* bs = Bs(buf);
        const int kk0 = kt * 32;
        #pragma unroll
        for (int p = 0; p < 4; p++) {
            int idx = p * 128 + tid;
            int row = idx >> 2;
            int ch  = idx & 3;
            const __half* src = A + (size_t)(bm + row) * K + kk0 + ch * 8;
            uint32_t dst = (uint32_t)__cvta_generic_to_shared(as + row * 48 + ch * 8);
            int sz = (bm + row) < M ? 16 : 0;
            asm volatile("cp.async.cg.shared.global [%0], [%1], 16, %2;"
                         :: "r"(dst), "l"(src), "r"(sz) : "memory");
        }
        #pragma unroll
        for (int p = 0; p < 4; p++) {
            int idx = p * 128 + tid;
            int row = idx >> 2;
            int ch  = idx & 3;
            const __half* src = Bt + (size_t)(bn + row) * K + kk0 + ch * 8;
            uint32_t dst = (uint32_t)__cvta_generic_to_shared(bs + row * 48 + ch * 8);
            asm volatile("cp.async.cg.shared.global [%0], [%1], 16;"
                         :: "r"(dst), "l"(src) : "memory");
        }
        asm volatile("cp.async.commit_group;" ::: "memory");
    };

    const int T = K >> 5;
    load_tile(0, 0);
    if (T > 1) load_tile(1, 1);

    int buf = 0;
    for (int kt = 0; kt < T; kt++) {
        if (kt + 1 < T) asm volatile("cp.async.wait_group 1;" ::: "memory");
        else            asm volatile("cp.async.wait_group 0;" ::: "memory");
        __syncthreads();

        if (kt + 2 < T) load_tile(kt + 2, (kt + 2) % 3);

        const __half* as = As(buf);
        const __half* bs = Bs(buf);

        #pragma unroll
        for (int s = 0; s < 2; s++) {
            uint32_t af[4][4];
            #pragma unroll
            for (int mt = 0; mt < 4; mt++) {
                int rb = mw * 64 + mt * 16;
                uint2 lo = *(const uint2*)(as + (rb + g)     * 48 + s * 16 + tig * 4);
                uint2 hi = *(const uint2*)(as + (rb + g + 8) * 48 + s * 16 + tig * 4);
                af[mt][0] = lo.x; af[mt][1] = hi.x; af[mt][2] = lo.y; af[mt][3] = hi.y;
            }
            #pragma unroll
            for (int nt = 0; nt < 8; nt++) {
                int cb = nw * 64 + nt * 8;
                uint2 bv = *(const uint2*)(bs + (cb + g) * 48 + s * 16 + tig * 4);
                #pragma unroll
                for (int mt = 0; mt < 4; mt++)
                    mma_f16(acc[mt][nt], af[mt][0], af[mt][1], af[mt][2], af[mt][3],
                            bv.x, bv.y);
            }
        }
        buf = (buf == 2) ? 0 : buf + 1;
    }

    float* Cf = (float*)Cv;
    __half* Ch = (__half*)Cv;
    #pragma unroll
    for (int mt = 0; mt < 4; mt++) {
        int r0 = bm + mw * 64 + mt * 16 + g;
        #pragma unroll
        for (int nt = 0; nt < 8; nt++) {
            int c0 = bn + nw * 64 + nt * 8 + 2 * tig;
            float b0 = bias[c0], b1 = bias[c0 + 1];
            #pragma unroll
            for (int h = 0; h < 2; h++) {
                int row = r0 + h * 8;
                if (row >= M) continue;
                float v0 = acc[mt][nt][h * 2 + 0] + b0;
                float v1 = acc[mt][nt][h * 2 + 1] + b1;
                if (EPI == 1) {
                    v0 = 0.5f * v0 * (1.f + erff(v0 * 0.70710678118654752f));
                    v1 = 0.5f * v1 * (1.f + erff(v1 * 0.70710678118654752f));
                    int pos = il16(c0);
                    __half2 hv = __floats2half2_rn(v0, v1);
                    *(__half2*)(Ch + (size_t)row * N + pos) = hv;
                } else {
                    if (EPI == 2) {
                        const float2 rr = *(const float2*)(res + (size_t)row * N + c0);
                        v0 += rr.x; v1 += rr.y;
                    }
                    float2 o; o.x = v0; o.y = v1;
                    *(float2*)(Cf + (size_t)row * N + c0) = o;
                }
            }
        }
    }
}

// ---------------- LayerNorm: fp16 interleaved out ----------------
__global__ void __launch_bounds__(256)
ln_h_kernel(const float* __restrict__ x, const float* __restrict__ g,
            const float* __restrict__ b, __half* __restrict__ o)
{
    int row = blockIdx.x;
    int tid = threadIdx.x;
    const float* xr = x + (size_t)row * DMODEL;
    float v0 = xr[tid], v1 = xr[tid + 256], v2 = xr[tid + 512];

    __shared__ float red[10];
    float s = v0 + v1 + v2;
    #pragma unroll
    for (int of = 16; of; of >>= 1) s += __shfl_xor_sync(~0u, s, of);
    if ((tid & 31) == 0) red[tid >> 5] = s;
    __syncthreads();
    if (tid == 0) {
        float t = 0.f;
        #pragma unroll
        for (int i = 0; i < 8; i++) t += red[i];
        red[8] = t * (1.f / 768.f);
    }
    __syncthreads();
    float mu = red[8];
    float d0 = v0 - mu, d1 = v1 - mu, d2 = v2 - mu;
    float q = d0 * d0 + d1 * d1 + d2 * d2;
    #pragma unroll
    for (int of = 16; of; of >>= 1) q += __shfl_xor_sync(~0u, q, of);
    if ((tid & 31) == 0) red[tid >> 5] = q;
    __syncthreads();
    if (tid == 0) {
        float t = 0.f;
        #pragma unroll
        for (int i = 0; i < 8; i++) t += red[i];
        red[9] = rsqrtf(t * (1.f / 768.f) + 1e-5f);
    }
    __syncthreads();
    float inv = red[9];
    __half* orow = o + (size_t)row * DMODEL;
    orow[il16(tid)]       = __float2half(d0 * inv * g[tid]       + b[tid]);
    orow[il16(tid + 256)] = __float2half(d1 * inv * g[tid + 256] + b[tid + 256]);
    orow[il16(tid + 512)] = __float2half(d2 * inv * g[tid + 512] + b[tid + 512]);
}

// ---------------- per-head QKV projection, fp16 mma ----------------
__global__ void __launch_bounds__(128)
qkv16_kernel(const __half* __restrict__ h,
             const __half* __restrict__ Wq, const __half* __restrict__ Wk,
             const __half* __restrict__ Wv,
             const float* __restrict__ bq, const float* __restrict__ bk,
             const float* __restrict__ bv,
             __half* __restrict__ q, __half* __restrict__ k, __half* __restrict__ vT)
{
    __shared__ __half Xs[64][80];
    __shared__ __half Ws[64][80];

    const int t0 = blockIdx.x * 64;
    const int hh = blockIdx.y;
    const int z  = blockIdx.z;
    const __half* W = ((z == 0) ? Wq : (z == 1) ? Wk : Wv) + hh * 64 * 64;
    const float* bb = ((z == 0) ? bq : (z == 1) ? bk : bv) + hh * 64;

    const int tid  = threadIdx.x;
    const int wid  = tid >> 5;
    const int lane = tid & 31;
    const int g    = lane >> 2;
    const int tig  = lane & 3;
    const int rb   = wid * 16;

    #pragma unroll
    for (int it = 0; it < 4; it++) {
        int idx = it * 128 + tid;
        int row = idx >> 3;
        int ch  = idx & 7;
        int tok = t0 + row;
        uint4 xv = make_uint4(0u, 0u, 0u, 0u);
        if (tok < NS) xv = *(const uint4*)(h + (size_t)tok * DMODEL + hh * 64 + ch * 8);
        *(uint4*)&Xs[row][ch * 8] = xv;
        *(uint4*)&Ws[row][ch * 8] = *(const uint4*)(W + row * 64 + ch * 8);
    }
    __syncthreads();

    float acc[8][4];
    #pragma unroll
    for (int nt = 0; nt < 8; nt++)
        #pragma unroll
        for (int c = 0; c < 4; c++) acc[nt][c] = 0.f;

    #pragma unroll
    for (int s = 0; s < 4; s++) {
        uint2 lo = *(const uint2*)&Xs[rb + g]    [s * 16 + tig * 4];
        uint2 hi = *(const uint2*)&Xs[rb + g + 8][s * 16 + tig * 4];
        #pragma unroll
        for (int nt = 0; nt < 8; nt++) {
            uint2 bv = *(const uint2*)&Ws[nt * 8 + g][s * 16 + tig * 4];
            mma_f16(acc[nt], lo.x, hi.x, lo.y, hi.y, bv.x, bv.y);
        }
    }

    __half* out = (z == 0) ? q : k;
    #pragma unroll
    for (int nt = 0; nt < 8; nt++) {
        int c0 = nt * 8 + 2 * tig;
        float b0 = bb[c0], b1 = bb[c0 + 1];
        #pragma unroll
        for (int hlf = 0; hlf < 2; hlf++) {
            int tok = t0 + rb + g + hlf * 8;
            if (tok >= NS) continue;
            float v0 = acc[nt][hlf * 2 + 0] + b0;
            float v1 = acc[nt][hlf * 2 + 1] + b1;
            if (z < 2) {
                __half2 hv = __floats2half2_rn(v0, v1);
                *(__half2*)(out + (size_t)tok * DMODEL + hh * 64 + il16(c0)) = hv;
            } else {
                int n  = tok / SEQ;
                int s_ = tok - n * SEQ;
                int b  = n * NHEAD + hh;
                int kp = il16(s_);
                vT[((size_t)b * 64 + c0)     * SEQP + kp] = __float2half(v0);
                vT[((size_t)b * 64 + c0 + 1) * SEQP + kp] = __float2half(v1);
            }
        }
    }
}

// ---------------- fused flash attention, fp16 mma ----------------
__global__ void __launch_bounds__(128)
attn16_kernel(const __half* __restrict__ q, const __half* __restrict__ k,
              const __half* __restrict__ vT, float* __restrict__ x)
{
    __shared__ __half Qs[64][80];
    __shared__ __half Ks[64][80];
    __shared__ __half Ps[64][80];
    __shared__ __half Vs[64][80];

    const int q0 = blockIdx.x * 64;
    const int b  = blockIdx.y;
    const int n  = b / NHEAD, hh = b - n * NHEAD;
    const int tid  = threadIdx.x;
    const int wid  = tid >> 5;
    const int lane = tid & 31;
    const int g    = lane >> 2;
    const int tig  = lane & 3;
    const int rb   = wid * 16;

    #pragma unroll
    for (int it = 0; it < 4; it++) {
        int idx = it * 128 + tid;
        int row = idx >> 3;
        int ch  = idx & 7;
        int qt = q0 + row;
        uint4 qv = make_uint4(0u, 0u, 0u, 0u);
        if (qt < SEQ) qv = *(const uint4*)(q + (size_t)(n * SEQ + qt) * DMODEL + hh * 64 + ch * 8);
        *(uint4*)&Qs[row][ch * 8] = qv;
    }

    float m_run[2] = {-1e30f, -1e30f};
    float l_run[2] = {0.f, 0.f};
    float acc_o[8][4];
    #pragma unroll
    for (int nt = 0; nt < 8; nt++)
        #pragma unroll
        for (int c = 0; c < 4; c++) acc_o[nt][c] = 0.f;

    for (int kt = 0; kt < 4; kt++) {
        const int k0 = kt * 64;
        __syncthreads();

        #pragma unroll
        for (int it = 0; it < 4; it++) {
            int idx = it * 128 + tid;
            int row = idx >> 3;
            int ch  = idx & 7;
            int ktok = k0 + row;
            uint4 kv = make_uint4(0u, 0u, 0u, 0u);
            if (ktok < SEQ)
                kv = *(const uint4*)(k + (size_t)(n * SEQ + ktok) * DMODEL + hh * 64 + ch * 8);
            *(uint4*)&Ks[row][ch * 8] = kv;
            *(uint4*)&Vs[row][ch * 8] =
                *(const uint4*)(vT + ((size_t)b * 64 + row) * SEQP + k0 + ch * 8);
        }
        __syncthreads();

        float s[8][4];
        #pragma unroll
        for (int nt = 0; nt < 8; nt++)
            #pragma unroll
            for (int c = 0; c < 4; c++) s[nt][c] = 0.f;

        #pragma unroll
        for (int ss = 0; ss < 4; ss++) {
            uint2 lo = *(const uint2*)&Qs[rb + g]    [ss * 16 + tig * 4];
            uint2 hi = *(const uint2*)&Qs[rb + g + 8][ss * 16 + tig * 4];
            #pragma unroll
            for (int nt = 0; nt < 8; nt++) {
                uint2 bv = *(const uint2*)&Ks[nt * 8 + g][ss * 16 + tig * 4];
                mma_f16(s[nt], lo.x, hi.x, lo.y, hi.y, bv.x, bv.y);
            }
        }

        #pragma unroll
        for (int nt = 0; nt < 8; nt++) {
            int c0 = k0 + nt * 8 + 2 * tig;
            s[nt][0] = (c0     < SEQ) ? s[nt][0] * 0.125f : -1e30f;
            s[nt][1] = (c0 + 1 < SEQ) ? s[nt][1] * 0.125f : -1e30f;
            s[nt][2] = (c0     < SEQ) ? s[nt][2] * 0.125f : -1e30f;
            s[nt][3] = (c0 + 1 < SEQ) ? s[nt][3] * 0.125f : -1e30f;
        }

        #pragma unroll
        for (int r = 0; r < 2; r++) {
            float mt_ = -1e30f;
            #pragma unroll
            for (int nt = 0; nt < 8; nt++)
                mt_ = fmaxf(mt_, fmaxf(s[nt][2 * r], s[nt][2 * r + 1]));
            mt_ = fmaxf(mt_, __shfl_xor_sync(~0u, mt_, 1));
            mt_ = fmaxf(mt_, __shfl_xor_sync(~0u, mt_, 2));
            float mnew = fmaxf(m_run[r], mt_);
            float sc = expf(m_run[r] - mnew);
            float rs = 0.f;
            #pragma unroll
            for (int nt = 0; nt < 8; nt++) {
                float p0 = expf(s[nt][2 * r]     - mnew);
                float p1 = expf(s[nt][2 * r + 1] - mnew);
                s[nt][2 * r] = p0; s[nt][2 * r + 1] = p1;
                rs += p0 + p1;
            }
            rs += __shfl_xor_sync(~0u, rs, 1);
            rs += __shfl_xor_sync(~0u, rs, 2);
            l_run[r] = l_run[r] * sc + rs;
            #pragma unroll
            for (int nt = 0; nt < 8; nt++) {
                acc_o[nt][2 * r]     *= sc;
                acc_o[nt][2 * r + 1] *= sc;
            }
            m_run[r] = mnew;
        }

        #pragma unroll
        for (int nt = 0; nt < 8; nt++) {
            int pc = il16(nt * 8 + 2 * tig);
            *(__half2*)&Ps[rb + g]    [pc] = __floats2half2_rn(s[nt][0], s[nt][1]);
            *(__half2*)&Ps[rb + g + 8][pc] = __floats2half2_rn(s[nt][2], s[nt][3]);
        }
        __syncwarp();

        #pragma unroll
        for (int ss = 0; ss < 4; ss++) {
            uint2 lo = *(const uint2*)&Ps[rb + g]    [ss * 16 + tig * 4];
            uint2 hi = *(const uint2*)&Ps[rb + g + 8][ss * 16 + tig * 4];
            #pragma unroll
            for (int nt = 0; nt < 8; nt++) {
                uint2 bv = *(const uint2*)&Vs[nt * 8 + g][ss * 16 + tig * 4];
                mma_f16(acc_o[nt], lo.x, hi.x, lo.y, hi.y, bv.x, bv.y);
            }
        }
    }

    #pragma unroll
    for (int r = 0; r < 2; r++) {
        int row = q0 + rb + g + r * 8;
        if (row >= SEQ) continue;
        float inv = 1.f / l_run[r];
        #pragma unroll
        for (int nt = 0; nt < 8; nt++) {
            int col = hh * 64 + nt * 8 + 2 * tig;
            float* px = x + (size_t)(n * SEQ + row) * DMODEL + col;
            float2 old = *(float2*)px;
            old.x += acc_o[nt][2 * r]     * inv;
            old.y += acc_o[nt][2 * r + 1] * inv;
            *(float2*)px = old;
        }
    }
}

// ---------------- head: parallel logits ----------------
__global__ void __launch_bounds__(256)
logits_kernel(const float* __restrict__ x, const float* __restrict__ Wh,
              const float* __restrict__ bh, float* __restrict__ lg)
{
    __shared__ float xs[DMODEL];
    int n  = blockIdx.y;
    int o  = blockIdx.x * 256 + threadIdx.x;
    for (int i = threadIdx.x; i < DMODEL; i += 256)
        xs[i] = x[(size_t)n * SEQ * DMODEL + i];
    __syncthreads();
    if (o >= OUTD) return;
    float a = bh[o];
    #pragma unroll 4
    for (int kk = 0; kk < DMODEL; kk++)
        a = fmaf(xs[kk], Wh[(size_t)kk * OUTD + o], a);
    lg[n * OUTD + o] = a;
}

// ---------------- head: per-image softmax ----------------
__global__ void __launch_bounds__(256)
head_softmax_kernel(const float* __restrict__ lg, float* __restrict__ out)
{
    __shared__ float red[256];
    int n = blockIdx.x, tid = threadIdx.x;
    const float* l = lg + n * OUTD;
    float m = -1e30f;
    for (int o = tid; o < OUTD; o += 256) m = fmaxf(m, l[o]);
    red[tid] = m; __syncthreads();
    for (int s = 128; s; s >>= 1) { if (tid < s) red[tid] = fmaxf(red[tid], red[tid + s]); __syncthreads(); }
    float mx = red[0]; __syncthreads();
    float sm = 0.f;
    for (int o = tid; o < OUTD; o += 256) sm += expf(l[o] - mx);
    red[tid] = sm; __syncthreads();
    for (int s = 128; s; s >>= 1) { if (tid < s) red[tid] += red[tid + s]; __syncthreads(); }
    float inv = 1.f / red[0];
    __syncthreads();
    for (int o = tid; o < OUTD; o += 256)
        out[(size_t)n * OUTD + o] = expf(l[o] - mx) * inv;
}

// ---------------- host orchestration ----------------
extern "C" void kernel_launch(void* const* d_in, const int* in_sizes, int n_in,
                              void* d_out, int out_size)
{
    const float* images   = (const float*)d_in[0];
    const float* W_map    = (const float*)d_in[1];
    const float* b_map    = (const float*)d_in[2];
    const float* cls      = (const float*)d_in[3];
    const float* pos      = (const float*)d_in[4];
    const float* ln1_g    = (const float*)d_in[5];
    const float* ln1_b    = (const float*)d_in[6];
    const float* Wq       = (const float*)d_in[7];
    const float* bq       = (const float*)d_in[8];
    const float* Wk       = (const float*)d_in[9];
    const float* bk       = (const float*)d_in[10];
    const float* Wv       = (const float*)d_in[11];
    const float* bv       = (const float*)d_in[12];
    const float* ln2_g    = (const float*)d_in[13];
    const float* ln2_b    = (const float*)d_in[14];
    const float* W1       = (const float*)d_in[15];
    const float* b1       = (const float*)d_in[16];
    const float* W2       = (const float*)d_in[17];
    const float* b2       = (const float*)d_in[18];
    const float* W_head   = (const float*)d_in[19];
    const float* b_head   = (const float*)d_in[20];
    float* out = (float*)d_out;

    __half *p_patches16, *p_h16, *p_mlp16, *p_q16, *p_k16, *p_vT16;
    __half *p_wmapT16, *p_w1T16, *p_w2T16, *p_wqT16, *p_wkT16, *p_wvT16;
    float *p_tokens, *p_x;
    cudaGetSymbolAddress((void**)&p_patches16, g_patches16);
    cudaGetSymbolAddress((void**)&p_tokens, g_tokens);
    cudaGetSymbolAddress((void**)&p_x, g_x);
    cudaGetSymbolAddress((void**)&p_h16, g_h16);
    cudaGetSymbolAddress((void**)&p_q16, g_q16);
    cudaGetSymbolAddress((void**)&p_k16, g_k16);
    cudaGetSymbolAddress((void**)&p_vT16, g_vT16);
    cudaGetSymbolAddress((void**)&p_mlp16, g_mlp16);
    cudaGetSymbolAddress((void**)&p_wmapT16, g_wmapT16);
    cudaGetSymbolAddress((void**)&p_w1T16, g_w1T16);
    cudaGetSymbolAddress((void**)&p_w2T16, g_w2T16);
    cudaGetSymbolAddress((void**)&p_wqT16, g_wqT16);
    cudaGetSymbolAddress((void**)&p_wkT16, g_wkT16);
    cudaGetSymbolAddress((void**)&p_wvT16, g_wvT16);

    cudaFuncSetAttribute(tgemm16<0>, cudaFuncAttributeMaxDynamicSharedMemorySize, TG16_SMEM);
    cudaFuncSetAttribute(tgemm16<1>, cudaFuncAttributeMaxDynamicSharedMemorySize, TG16_SMEM);
    cudaFuncSetAttribute(tgemm16<2>, cudaFuncAttributeMaxDynamicSharedMemorySize, TG16_SMEM);

    // 0) weight prep
    {
        dim3 gmap(DMODEL / 32, IN_DIM / 32, 1);
        cvtT16_kernel<<<gmap, 256>>>(W_map, p_wmapT16, IN_DIM, DMODEL);
        dim3 g1(MLPD / 32, DMODEL / 32, LAYERS);
        cvtT16_kernel<<<g1, 256>>>(W1, p_w1T16, DMODEL, MLPD);
        dim3 g2(DMODEL / 32, MLPD / 32, LAYERS);
        cvtT16_kernel<<<g2, 256>>>(W2, p_w2T16, MLPD, DMODEL);
        dim3 gq(2, 2, LAYERS * NHEAD);
        cvtT16_kernel<<<gq, 256>>>(Wq, p_wqT16, DHEAD, DHEAD);
        cvtT16_kernel<<<gq, 256>>>(Wk, p_wkT16, DHEAD, DHEAD);
        cvtT16_kernel<<<gq, 256>>>(Wv, p_wvT16, DHEAD, DHEAD);
    }

    // 1) patchify + embed + assemble
    patchify_kernel<<<(NP * IN_DIM) / 256, 256>>>(images);
    {
        dim3 grid(DMODEL / 128, NP / 128);
        tgemm16<0><<<grid, 128, TG16_SMEM>>>(p_patches16, p_wmapT16, b_map, nullptr,
                                             p_tokens, NP, DMODEL, IN_DIM);
    }
    assemble_kernel<<<(NS * DMODEL) / 256, 256>>>(p_tokens, cls, pos);

    // 2) transformer blocks
    for (int l = 0; l < LAYERS; l++) {
        ln_h_kernel<<<NS, 256>>>(p_x, ln1_g + l * DMODEL, ln1_b + l * DMODEL, p_h16);

        {
            dim3 grid((NS + 63) / 64, NHEAD, 3);
            qkv16_kernel<<<grid, 128>>>(p_h16,
                p_wqT16 + (size_t)l * NHEAD * DHEAD * DHEAD,
                p_wkT16 + (size_t)l * NHEAD * DHEAD * DHEAD,
                p_wvT16 + (size_t)l * NHEAD * DHEAD * DHEAD,
                bq + (size_t)l * NHEAD * DHEAD,
                bk + (size_t)l * NHEAD * DHEAD,
                bv + (size_t)l * NHEAD * DHEAD,
                p_q16, p_k16, p_vT16);
        }
        {
            dim3 grid((SEQ + 63) / 64, NB * NHEAD);
            attn16_kernel<<<grid, 128>>>(p_q16, p_k16, p_vT16, p_x);
        }

        ln_h_kernel<<<NS, 256>>>(p_x, ln2_g + l * DMODEL, ln2_b + l * DMODEL, p_h16);
        {
            dim3 grid(MLPD / 128, (NS + 127) / 128);
            tgemm16<1><<<grid, 128, TG16_SMEM>>>(p_h16, p_w1T16 + (size_t)l * DMODEL * MLPD,
                                                 b1 + (size_t)l * MLPD, nullptr,
                                                 p_mlp16, NS, MLPD, DMODEL);
        }
        {
            dim3 grid(DMODEL / 128, (NS + 127) / 128);
            tgemm16<2><<<grid, 128, TG16_SMEM>>>(p_mlp16, p_w2T16 + (size_t)l * MLPD * DMODEL,
                                                 b2 + (size_t)l * DMODEL, p_x,
                                                 p_x, NS, DMODEL, MLPD);
        }
    }

    // 3) head: logits (parallel) + softmax
    {
        dim3 grid((OUTD + 255) / 256, NB);
        logits_kernel<<<grid, 256>>>(p_x, W_head, b_head, p_tokens);
    }
    head_softmax_kernel<<<NB, 256>>>(p_tokens, out);
}

// round 14
// speedup vs baseline: 1.1582x; 1.0161x over previous
#include <cuda_runtime.h>
#include <cuda_bf16.h>
#include <cuda_fp16.h>
#include <math.h>
#include <cstdint>

// ---------------- problem constants ----------------
#define NB     32
#define SEQ    197
#define SEQP   256
#define DMODEL 768
#define NHEAD  12
#define DHEAD  64
#define LAYERS 12
#define MLPD   3072
#define OUTD   1000
#define PPATCH 196
#define IN_DIM 768
#define NS     (NB * SEQ)       // 6304 tokens
#define NP     (NB * PPATCH)    // 6272 patches

// ---------------- device scratch ----------------
__device__ __half g_patches16[NP * IN_DIM];
__device__ float  g_tokens[NP * DMODEL];           // embed output; also logits scratch
__device__ float  g_x[NS * DMODEL];
__device__ __half g_h16[NS * DMODEL];
__device__ __half g_q16[NS * DMODEL];
__device__ __half g_k16[NS * DMODEL];
__device__ __half g_vT16[NB * NHEAD * 64 * SEQP];
__device__ __half g_mlp16[NS * MLPD];
__device__ __half g_wmapT16[DMODEL * IN_DIM];
__device__ __half g_w1T16[LAYERS * MLPD * DMODEL];
__device__ __half g_w2T16[LAYERS * DMODEL * MLPD];
__device__ __half g_wqT16[LAYERS * NHEAD * DHEAD * DHEAD];
__device__ __half g_wkT16[LAYERS * NHEAD * DHEAD * DHEAD];
__device__ __half g_wvT16[LAYERS * NHEAD * DHEAD * DHEAD];

__device__ __forceinline__ int il16(int c)
{
    int r = c & 15;
    int p = ((r & 7) >> 1) * 4 + ((r >> 3) << 1) + (r & 1);
    return (c & ~15) | p;
}
__device__ __forceinline__ int inv16(int c)
{
    int r = c & 15;
    int k = (((r & 3) < 2) ? 0 : 8) + ((r >> 2) << 1) + (r & 1);
    return (c & ~15) | k;
}

__device__ __forceinline__ void mma_f16(float* c, uint32_t a0, uint32_t a1,
                                        uint32_t a2, uint32_t a3,
                                        uint32_t b0, uint32_t b1)
{
    asm volatile(
        "mma.sync.aligned.m16n8k16.row.col.f32.f16.f16.f32 "
        "{%0,%1,%2,%3},{%4,%5,%6,%7},{%8,%9},{%0,%1,%2,%3};"
        : "+f"(c[0]), "+f"(c[1]), "+f"(c[2]), "+f"(c[3])
        : "r"(a0), "r"(a1), "r"(a2), "r"(a3), "r"(b0), "r"(b1));
}

// ---------------- weight prep ----------------
__global__ void __launch_bounds__(256)
cvtT16_kernel(const float* __restrict__ src, __half* __restrict__ dst, int R, int C)
{
    __shared__ float t[32][33];
    size_t zoff = (size_t)blockIdx.z * R * C;
    int bx = blockIdx.x * 32;
    int by = blockIdx.y * 32;
    int tx = threadIdx.x & 31;
    int ty = threadIdx.x >> 5;
    #pragma unroll
    for (int i = 0; i < 32; i += 8)
        t[ty + i][tx] = src[zoff + (size_t)(by + ty + i) * C + bx + tx];
    __syncthreads();
    int kp = il16(by + tx);
    #pragma unroll
    for (int i = 0; i < 32; i += 8)
        dst[zoff + (size_t)(bx + ty + i) * R + kp] = __float2half(t[tx][ty + i]);
}

// ---------------- patchify ----------------
__global__ void __launch_bounds__(256)
patchify_kernel(const float* __restrict__ img)
{
    int idx = blockIdx.x * 256 + threadIdx.x;
    if (idx >= NP * IN_DIM) return;
    int t = idx / IN_DIM;
    int ep = idx - t * IN_DIM;
    int e = inv16(ep);
    int n = t / PPATCH;
    int p = t - n * PPATCH;
    int py = p / 14, px = p - py * 14;
    int c  = e >> 8;
    int r  = e & 255;
    int ph = r >> 4, pw = r & 15;
    g_patches16[idx] = __float2half(
        img[(((size_t)n * 3 + c) * 224 + (py * 16 + ph)) * 224 + px * 16 + pw]);
}

// ---------------- assemble ----------------
__global__ void __launch_bounds__(256)
assemble_kernel(const float* __restrict__ tokens, const float* __restrict__ cls,
                const float* __restrict__ pos)
{
    int idx = blockIdx.x * 256 + threadIdx.x;
    if (idx >= NS * DMODEL) return;
    int t = idx / DMODEL;
    int d = idx - t * DMODEL;
    int n = t / SEQ;
    int s = t - n * SEQ;
    float v = (s == 0) ? cls[d] : tokens[((size_t)(n * PPATCH + s - 1)) * DMODEL + d];
    g_x[idx] = v + pos[s * DMODEL + d];
}

// ---------------- fp16 tensor-core GEMM (proven R11/R13 config) ----------
#define TG16_STAGE 24576
#define TG16_SMEM  (3 * TG16_STAGE)   // 73728 bytes

template<int EPI>
__global__ void __launch_bounds__(128, 2)
tgemm16(const __half* __restrict__ A, const __half* __restrict__ Bt,
        const float* __restrict__ bias, const float* __restrict__ res,
        void* __restrict__ Cv, int M, int N, int K)
{
    extern __shared__ char sm16[];

    const int tid  = threadIdx.x;
    const int wid  = tid >> 5;
    const int lane = tid & 31;
    const int g    = lane >> 2;
    const int tig  = lane & 3;
    const int mw   = wid & 1;
    const int nw   = wid >> 1;
    const int bm   = blockIdx.y * 128;
    const int bn   = blockIdx.x * 128;

    float acc[4][8][4];
    #pragma unroll
    for (int i = 0; i < 4; i++)
        #pragma unroll
        for (int j = 0; j < 8; j++)
            #pragma unroll
            for (int c = 0; c < 4; c++) acc[i][j][c] = 0.f;

    auto As = [&](int buf) { return (__half*)(sm16 + buf * TG16_STAGE); };
    auto Bs = [&](int buf) { return (__half*)(sm16 + buf * TG16_STAGE + 12288); };

    auto load_tile = [&](int kt, int buf) {
        __half* as = As(buf);
        __half* bs = Bs(buf);
        const int kk0 = kt * 32;
        #pragma unroll
        for (int p = 0; p < 4; p++) {
            int idx = p * 128 + tid;
            int row = idx >> 2;
            int ch  = idx & 3;
            const __half* src = A + (size_t)(bm + row) * K + kk0 + ch * 8;
            uint32_t dst = (uint32_t)__cvta_generic_to_shared(as + row * 48 + ch * 8);
            int sz = (bm + row) < M ? 16 : 0;
            asm volatile("cp.async.cg.shared.global [%0], [%1], 16, %2;"
                         :: "r"(dst), "l"(src), "r"(sz) : "memory");
        }
        #pragma unroll
        for (int p = 0; p < 4; p++) {
            int idx = p * 128 + tid;
            int row = idx >> 2;
            int ch  = idx & 3;
            const __half* src = Bt + (size_t)(bn + row) * K + kk0 + ch * 8;
            uint32_t dst = (uint32_t)__cvta_generic_to_shared(bs + row * 48 + ch * 8);
            asm volatile("cp.async.cg.shared.global [%0], [%1], 16;"
                         :: "r"(dst), "l"(src) : "memory");
        }
        asm volatile("cp.async.commit_group;" ::: "memory");
    };

    const int T = K >> 5;
    load_tile(0, 0);
    if (T > 1) load_tile(1, 1);

    int buf = 0;
    for (int kt = 0; kt < T; kt++) {
        if (kt + 1 < T) asm volatile("cp.async.wait_group 1;" ::: "memory");
        else            asm volatile("cp.async.wait_group 0;" ::: "memory");
        __syncthreads();

        if (kt + 2 < T) load_tile(kt + 2, (kt + 2) % 3);

        const __half* as = As(buf);
        const __half* bs = Bs(buf);

        #pragma unroll
        for (int s = 0; s < 2; s++) {
            uint32_t af[4][4];
            #pragma unroll
            for (int mt = 0; mt < 4; mt++) {
                int rb = mw * 64 + mt * 16;
                uint2 lo = *(const uint2*)(as + (rb + g)     * 48 + s * 16 + tig * 4);
                uint2 hi = *(const uint2*)(as + (rb + g + 8) * 48 + s * 16 + tig * 4);
                af[mt][0] = lo.x; af[mt][1] = hi.x; af[mt][2] = lo.y; af[mt][3] = hi.y;
            }
            #pragma unroll
            for (int nt = 0; nt < 8; nt++) {
                int cb = nw * 64 + nt * 8;
                uint2 bv = *(const uint2*)(bs + (cb + g) * 48 + s * 16 + tig * 4);
                #pragma unroll
                for (int mt = 0; mt < 4; mt++)
                    mma_f16(acc[mt][nt], af[mt][0], af[mt][1], af[mt][2], af[mt][3],
                            bv.x, bv.y);
            }
        }
        buf = (buf == 2) ? 0 : buf + 1;
    }

    float* Cf = (float*)Cv;
    __half* Ch = (__half*)Cv;
    #pragma unroll
    for (int mt = 0; mt < 4; mt++) {
        int r0 = bm + mw * 64 + mt * 16 + g;
        #pragma unroll
        for (int nt = 0; nt < 8; nt++) {
            int c0 = bn + nw * 64 + nt * 8 + 2 * tig;
            float b0 = bias[c0], b1 = bias[c0 + 1];
            #pragma unroll
            for (int h = 0; h < 2; h++) {
                int row = r0 + h * 8;
                if (row >= M) continue;
                float v0 = acc[mt][nt][h * 2 + 0] + b0;
                float v1 = acc[mt][nt][h * 2 + 1] + b1;
                if (EPI == 1) {
                    v0 = 0.5f * v0 * (1.f + erff(v0 * 0.70710678118654752f));
                    v1 = 0.5f * v1 * (1.f + erff(v1 * 0.70710678118654752f));
                    int pos = il16(c0);
                    __half2 hv = __floats2half2_rn(v0, v1);
                    *(__half2*)(Ch + (size_t)row * N + pos) = hv;
                } else {
                    if (EPI == 2) {
                        const float2 rr = *(const float2*)(res + (size_t)row * N + c0);
                        v0 += rr.x; v1 += rr.y;
                    }
                    float2 o; o.x = v0; o.y = v1;
                    *(float2*)(Cf + (size_t)row * N + c0) = o;
                }
            }
        }
    }
}

// ---------------- LayerNorm: warp-per-row, zero block barriers ----------------
// grid = NS/8 blocks of 8 warps; each warp owns one token row.
__global__ void __launch_bounds__(256)
ln_h_kernel(const float* __restrict__ x, const float* __restrict__ g,
            const float* __restrict__ b, __half* __restrict__ o)
{
    const int row  = blockIdx.x * 8 + (threadIdx.x >> 5);
    const int lane = threadIdx.x & 31;
    const float* xr = x + (size_t)row * DMODEL;

    float v[24];
    float s = 0.f;
    #pragma unroll
    for (int c = 0; c < 6; c++) {
        float4 t = *(const float4*)(xr + c * 128 + lane * 4);
        v[c * 4 + 0] = t.x; v[c * 4 + 1] = t.y;
        v[c * 4 + 2] = t.z; v[c * 4 + 3] = t.w;
        s += (t.x + t.y) + (t.z + t.w);
    }
    #pragma unroll
    for (int of = 16; of; of >>= 1) s += __shfl_xor_sync(~0u, s, of);
    const float mu = s * (1.f / 768.f);

    float q = 0.f;
    #pragma unroll
    for (int i = 0; i < 24; i++) {
        float d = v[i] - mu;
        v[i] = d;
        q = fmaf(d, d, q);
    }
    #pragma unroll
    for (int of = 16; of; of >>= 1) q += __shfl_xor_sync(~0u, q, of);
    const float inv = rsqrtf(q * (1.f / 768.f) + 1e-5f);

    __half* orow = o + (size_t)row * DMODEL;
    #pragma unroll
    for (int c = 0; c < 6; c++) {
        int d0 = c * 128 + lane * 4;
        const float4 gg = *(const float4*)(g + d0);
        const float4 bb = *(const float4*)(b + d0);
        float o0 = v[c * 4 + 0] * inv * gg.x + bb.x;
        float o1 = v[c * 4 + 1] * inv * gg.y + bb.y;
        float o2 = v[c * 4 + 2] * inv * gg.z + bb.z;
        float o3 = v[c * 4 + 3] * inv * gg.w + bb.w;
        *(__half2*)(orow + il16(d0))     = __floats2half2_rn(o0, o1);
        *(__half2*)(orow + il16(d0 + 2)) = __floats2half2_rn(o2, o3);
    }
}

// ---------------- per-head QKV projection, fp16 mma ----------------
__global__ void __launch_bounds__(128)
qkv16_kernel(const __half* __restrict__ h,
             const __half* __restrict__ Wq, const __half* __restrict__ Wk,
             const __half* __restrict__ Wv,
             const float* __restrict__ bq, const float* __restrict__ bk,
             const float* __restrict__ bv,
             __half* __restrict__ q, __half* __restrict__ k, __half* __restrict__ vT)
{
    __shared__ __half Xs[64][80];
    __shared__ __half Ws[64][80];

    const int t0 = blockIdx.x * 64;
    const int hh = blockIdx.y;
    const int z  = blockIdx.z;
    const __half* W = ((z == 0) ? Wq : (z == 1) ? Wk : Wv) + hh * 64 * 64;
    const float* bb = ((z == 0) ? bq : (z == 1) ? bk : bv) + hh * 64;

    const int tid  = threadIdx.x;
    const int wid  = tid >> 5;
    const int lane = tid & 31;
    const int g    = lane >> 2;
    const int tig  = lane & 3;
    const int rb   = wid * 16;

    #pragma unroll
    for (int it = 0; it < 4; it++) {
        int idx = it * 128 + tid;
        int row = idx >> 3;
        int ch  = idx & 7;
        int tok = t0 + row;
        uint4 xv = make_uint4(0u, 0u, 0u, 0u);
        if (tok < NS) xv = *(const uint4*)(h + (size_t)tok * DMODEL + hh * 64 + ch * 8);
        *(uint4*)&Xs[row][ch * 8] = xv;
        *(uint4*)&Ws[row][ch * 8] = *(const uint4*)(W + row * 64 + ch * 8);
    }
    __syncthreads();

    float acc[8][4];
    #pragma unroll
    for (int nt = 0; nt < 8; nt++)
        #pragma unroll
        for (int c = 0; c < 4; c++) acc[nt][c] = 0.f;

    #pragma unroll
    for (int s = 0; s < 4; s++) {
        uint2 lo = *(const uint2*)&Xs[rb + g]    [s * 16 + tig * 4];
        uint2 hi = *(const uint2*)&Xs[rb + g + 8][s * 16 + tig * 4];
        #pragma unroll
        for (int nt = 0; nt < 8; nt++) {
            uint2 bv = *(const uint2*)&Ws[nt * 8 + g][s * 16 + tig * 4];
            mma_f16(acc[nt], lo.x, hi.x, lo.y, hi.y, bv.x, bv.y);
        }
    }

    __half* out = (z == 0) ? q : k;
    #pragma unroll
    for (int nt = 0; nt < 8; nt++) {
        int c0 = nt * 8 + 2 * tig;
        float b0 = bb[c0], b1 = bb[c0 + 1];
        #pragma unroll
        for (int hlf = 0; hlf < 2; hlf++) {
            int tok = t0 + rb + g + hlf * 8;
            if (tok >= NS) continue;
            float v0 = acc[nt][hlf * 2 + 0] + b0;
            float v1 = acc[nt][hlf * 2 + 1] + b1;
            if (z < 2) {
                __half2 hv = __floats2half2_rn(v0, v1);
                *(__half2*)(out + (size_t)tok * DMODEL + hh * 64 + il16(c0)) = hv;
            } else {
                int n  = tok / SEQ;
                int s_ = tok - n * SEQ;
                int b  = n * NHEAD + hh;
                int kp = il16(s_);
                vT[((size_t)b * 64 + c0)     * SEQP + kp] = __float2half(v0);
                vT[((size_t)b * 64 + c0 + 1) * SEQP + kp] = __float2half(v1);
            }
        }
    }
}

// ---------------- fused flash attention, fp16 mma ----------------
__global__ void __launch_bounds__(128)
attn16_kernel(const __half* __restrict__ q, const __half* __restrict__ k,
              const __half* __restrict__ vT, float* __restrict__ x)
{
    __shared__ __half Qs[64][80];
    __shared__ __half Ks[64][80];
    __shared__ __half Ps[64][80];
    __shared__ __half Vs[64][80];

    const int q0 = blockIdx.x * 64;
    const int b  = blockIdx.y;
    const int n  = b / NHEAD, hh = b - n * NHEAD;
    const int tid  = threadIdx.x;
    const int wid  = tid >> 5;
    const int lane = tid & 31;
    const int g    = lane >> 2;
    const int tig  = lane & 3;
    const int rb   = wid * 16;

    #pragma unroll
    for (int it = 0; it < 4; it++) {
        int idx = it * 128 + tid;
        int row = idx >> 3;
        int ch  = idx & 7;
        int qt = q0 + row;
        uint4 qv = make_uint4(0u, 0u, 0u, 0u);
        if (qt < SEQ) qv = *(const uint4*)(q + (size_t)(n * SEQ + qt) * DMODEL + hh * 64 + ch * 8);
        *(uint4*)&Qs[row][ch * 8] = qv;
    }

    float m_run[2] = {-1e30f, -1e30f};
    float l_run[2] = {0.f, 0.f};
    float acc_o[8][4];
    #pragma unroll
    for (int nt = 0; nt < 8; nt++)
        #pragma unroll
        for (int c = 0; c < 4; c++) acc_o[nt][c] = 0.f;

    for (int kt = 0; kt < 4; kt++) {
        const int k0 = kt * 64;
        __syncthreads();

        #pragma unroll
        for (int it = 0; it < 4; it++) {
            int idx = it * 128 + tid;
            int row = idx >> 3;
            int ch  = idx & 7;
            int ktok = k0 + row;
            uint4 kv = make_uint4(0u, 0u, 0u, 0u);
            if (ktok < SEQ)
                kv = *(const uint4*)(k + (size_t)(n * SEQ + ktok) * DMODEL + hh * 64 + ch * 8);
            *(uint4*)&Ks[row][ch * 8] = kv;
            *(uint4*)&Vs[row][ch * 8] =
                *(const uint4*)(vT + ((size_t)b * 64 + row) * SEQP + k0 + ch * 8);
        }
        __syncthreads();

        float s[8][4];
        #pragma unroll
        for (int nt = 0; nt < 8; nt++)
            #pragma unroll
            for (int c = 0; c < 4; c++) s[nt][c] = 0.f;

        #pragma unroll
        for (int ss = 0; ss < 4; ss++) {
            uint2 lo = *(const uint2*)&Qs[rb + g]    [ss * 16 + tig * 4];
            uint2 hi = *(const uint2*)&Qs[rb + g + 8][ss * 16 + tig * 4];
            #pragma unroll
            for (int nt = 0; nt < 8; nt++) {
                uint2 bv = *(const uint2*)&Ks[nt * 8 + g][ss * 16 + tig * 4];
                mma_f16(s[nt], lo.x, hi.x, lo.y, hi.y, bv.x, bv.y);
            }
        }

        #pragma unroll
        for (int nt = 0; nt < 8; nt++) {
            int c0 = k0 + nt * 8 + 2 * tig;
            s[nt][0] = (c0     < SEQ) ? s[nt][0] * 0.125f : -1e30f;
            s[nt][1] = (c0 + 1 < SEQ) ? s[nt][1] * 0.125f : -1e30f;
            s[nt][2] = (c0     < SEQ) ? s[nt][2] * 0.125f : -1e30f;
            s[nt][3] = (c0 + 1 < SEQ) ? s[nt][3] * 0.125f : -1e30f;
        }

        #pragma unroll
        for (int r = 0; r < 2; r++) {
            float mt_ = -1e30f;
            #pragma unroll
            for (int nt = 0; nt < 8; nt++)
                mt_ = fmaxf(mt_, fmaxf(s[nt][2 * r], s[nt][2 * r + 1]));
            mt_ = fmaxf(mt_, __shfl_xor_sync(~0u, mt_, 1));
            mt_ = fmaxf(mt_, __shfl_xor_sync(~0u, mt_, 2));
            float mnew = fmaxf(m_run[r], mt_);
            float sc = expf(m_run[r] - mnew);
            float rs = 0.f;
            #pragma unroll
            for (int nt = 0; nt < 8; nt++) {
                float p0 = expf(s[nt][2 * r]     - mnew);
                float p1 = expf(s[nt][2 * r + 1] - mnew);
                s[nt][2 * r] = p0; s[nt][2 * r + 1] = p1;
                rs += p0 + p1;
            }
            rs += __shfl_xor_sync(~0u, rs, 1);
            rs += __shfl_xor_sync(~0u, rs, 2);
            l_run[r] = l_run[r] * sc + rs;
            #pragma unroll
            for (int nt = 0; nt < 8; nt++) {
                acc_o[nt][2 * r]     *= sc;
                acc_o[nt][2 * r + 1] *= sc;
            }
            m_run[r] = mnew;
        }

        #pragma unroll
        for (int nt = 0; nt < 8; nt++) {
            int pc = il16(nt * 8 + 2 * tig);
            *(__half2*)&Ps[rb + g]    [pc] = __floats2half2_rn(s[nt][0], s[nt][1]);
            *(__half2*)&Ps[rb + g + 8][pc] = __floats2half2_rn(s[nt][2], s[nt][3]);
        }
        __syncwarp();

        #pragma unroll
        for (int ss = 0; ss < 4; ss++) {
            uint2 lo = *(const uint2*)&Ps[rb + g]    [ss * 16 + tig * 4];
            uint2 hi = *(const uint2*)&Ps[rb + g + 8][ss * 16 + tig * 4];
            #pragma unroll
            for (int nt = 0; nt < 8; nt++) {
                uint2 bv = *(const uint2*)&Vs[nt * 8 + g][ss * 16 + tig * 4];
                mma_f16(acc_o[nt], lo.x, hi.x, lo.y, hi.y, bv.x, bv.y);
            }
        }
    }

    #pragma unroll
    for (int r = 0; r < 2; r++) {
        int row = q0 + rb + g + r * 8;
        if (row >= SEQ) continue;
        float inv = 1.f / l_run[r];
        #pragma unroll
        for (int nt = 0; nt < 8; nt++) {
            int col = hh * 64 + nt * 8 + 2 * tig;
            float* px = x + (size_t)(n * SEQ + row) * DMODEL + col;
            float2 old = *(float2*)px;
            old.x += acc_o[nt][2 * r]     * inv;
            old.y += acc_o[nt][2 * r + 1] * inv;
            *(float2*)px = old;
        }
    }
}

// ---------------- head: parallel logits ----------------
__global__ void __launch_bounds__(256)
logits_kernel(const float* __restrict__ x, const float* __restrict__ Wh,
              const float* __restrict__ bh, float* __restrict__ lg)
{
    __shared__ float xs[DMODEL];
    int n  = blockIdx.y;
    int o  = blockIdx.x * 256 + threadIdx.x;
    for (int i = threadIdx.x; i < DMODEL; i += 256)
        xs[i] = x[(size_t)n * SEQ * DMODEL + i];
    __syncthreads();
    if (o >= OUTD) return;
    float a = bh[o];
    #pragma unroll 4
    for (int kk = 0; kk < DMODEL; kk++)
        a = fmaf(xs[kk], Wh[(size_t)kk * OUTD + o], a);
    lg[n * OUTD + o] = a;
}

// ---------------- head: per-image softmax ----------------
__global__ void __launch_bounds__(256)
head_softmax_kernel(const float* __restrict__ lg, float* __restrict__ out)
{
    __shared__ float red[256];
    int n = blockIdx.x, tid = threadIdx.x;
    const float* l = lg + n * OUTD;
    float m = -1e30f;
    for (int o = tid; o < OUTD; o += 256) m = fmaxf(m, l[o]);
    red[tid] = m; __syncthreads();
    for (int s = 128; s; s >>= 1) { if (tid < s) red[tid] = fmaxf(red[tid], red[tid + s]); __syncthreads(); }
    float mx = red[0]; __syncthreads();
    float sm = 0.f;
    for (int o = tid; o < OUTD; o += 256) sm += expf(l[o] - mx);
    red[tid] = sm; __syncthreads();
    for (int s = 128; s; s >>= 1) { if (tid < s) red[tid] += red[tid + s]; __syncthreads(); }
    float inv = 1.f / red[0];
    __syncthreads();
    for (int o = tid; o < OUTD; o += 256)
        out[(size_t)n * OUTD + o] = expf(l[o] - mx) * inv;
}

// ---------------- host orchestration ----------------
extern "C" void kernel_launch(void* const* d_in, const int* in_sizes, int n_in,
                              void* d_out, int out_size)
{
    const float* images   = (const float*)d_in[0];
    const float* W_map    = (const float*)d_in[1];
    const float* b_map    = (const float*)d_in[2];
    const float* cls      = (const float*)d_in[3];
    const float* pos      = (const float*)d_in[4];
    const float* ln1_g    = (const float*)d_in[5];
    const float* ln1_b    = (const float*)d_in[6];
    const float* Wq       = (const float*)d_in[7];
    const float* bq       = (const float*)d_in[8];
    const float* Wk       = (const float*)d_in[9];
    const float* bk       = (const float*)d_in[10];
    const float* Wv       = (const float*)d_in[11];
    const float* bv       = (const float*)d_in[12];
    const float* ln2_g    = (const float*)d_in[13];
    const float* ln2_b    = (const float*)d_in[14];
    const float* W1       = (const float*)d_in[15];
    const float* b1       = (const float*)d_in[16];
    const float* W2       = (const float*)d_in[17];
    const float* b2       = (const float*)d_in[18];
    const float* W_head   = (const float*)d_in[19];
    const float* b_head   = (const float*)d_in[20];
    float* out = (float*)d_out;

    __half *p_patches16, *p_h16, *p_mlp16, *p_q16, *p_k16, *p_vT16;
    __half *p_wmapT16, *p_w1T16, *p_w2T16, *p_wqT16, *p_wkT16, *p_wvT16;
    float *p_tokens, *p_x;
    cudaGetSymbolAddress((void**)&p_patches16, g_patches16);
    cudaGetSymbolAddress((void**)&p_tokens, g_tokens);
    cudaGetSymbolAddress((void**)&p_x, g_x);
    cudaGetSymbolAddress((void**)&p_h16, g_h16);
    cudaGetSymbolAddress((void**)&p_q16, g_q16);
    cudaGetSymbolAddress((void**)&p_k16, g_k16);
    cudaGetSymbolAddress((void**)&p_vT16, g_vT16);
    cudaGetSymbolAddress((void**)&p_mlp16, g_mlp16);
    cudaGetSymbolAddress((void**)&p_wmapT16, g_wmapT16);
    cudaGetSymbolAddress((void**)&p_w1T16, g_w1T16);
    cudaGetSymbolAddress((void**)&p_w2T16, g_w2T16);
    cudaGetSymbolAddress((void**)&p_wqT16, g_wqT16);
    cudaGetSymbolAddress((void**)&p_wkT16, g_wkT16);
    cudaGetSymbolAddress((void**)&p_wvT16, g_wvT16);

    cudaFuncSetAttribute(tgemm16<0>, cudaFuncAttributeMaxDynamicSharedMemorySize, TG16_SMEM);
    cudaFuncSetAttribute(tgemm16<1>, cudaFuncAttributeMaxDynamicSharedMemorySize, TG16_SMEM);
    cudaFuncSetAttribute(tgemm16<2>, cudaFuncAttributeMaxDynamicSharedMemorySize, TG16_SMEM);

    // 0) weight prep
    {
        dim3 gmap(DMODEL / 32, IN_DIM / 32, 1);
        cvtT16_kernel<<<gmap, 256>>>(W_map, p_wmapT16, IN_DIM, DMODEL);
        dim3 g1(MLPD / 32, DMODEL / 32, LAYERS);
        cvtT16_kernel<<<g1, 256>>>(W1, p_w1T16, DMODEL, MLPD);
        dim3 g2(DMODEL / 32, MLPD / 32, LAYERS);
        cvtT16_kernel<<<g2, 256>>>(W2, p_w2T16, MLPD, DMODEL);
        dim3 gq(2, 2, LAYERS * NHEAD);
        cvtT16_kernel<<<gq, 256>>>(Wq, p_wqT16, DHEAD, DHEAD);
        cvtT16_kernel<<<gq, 256>>>(Wk, p_wkT16, DHEAD, DHEAD);
        cvtT16_kernel<<<gq, 256>>>(Wv, p_wvT16, DHEAD, DHEAD);
    }

    // 1) patchify + embed + assemble
    patchify_kernel<<<(NP * IN_DIM) / 256, 256>>>(images);
    {
        dim3 grid(DMODEL / 128, NP / 128);
        tgemm16<0><<<grid, 128, TG16_SMEM>>>(p_patches16, p_wmapT16, b_map, nullptr,
                                             p_tokens, NP, DMODEL, IN_DIM);
    }
    assemble_kernel<<<(NS * DMODEL) / 256, 256>>>(p_tokens, cls, pos);

    // 2) transformer blocks
    for (int l = 0; l < LAYERS; l++) {
        ln_h_kernel<<<NS / 8, 256>>>(p_x, ln1_g + l * DMODEL, ln1_b + l * DMODEL, p_h16);

        {
            dim3 grid((NS + 63) / 64, NHEAD, 3);
            qkv16_kernel<<<grid, 128>>>(p_h16,
                p_wqT16 + (size_t)l * NHEAD * DHEAD * DHEAD,
                p_wkT16 + (size_t)l * NHEAD * DHEAD * DHEAD,
                p_wvT16 + (size_t)l * NHEAD * DHEAD * DHEAD,
                bq + (size_t)l * NHEAD * DHEAD,
                bk + (size_t)l * NHEAD * DHEAD,
                bv + (size_t)l * NHEAD * DHEAD,
                p_q16, p_k16, p_vT16);
        }
        {
            dim3 grid((SEQ + 63) / 64, NB * NHEAD);
            attn16_kernel<<<grid, 128>>>(p_q16, p_k16, p_vT16, p_x);
        }

        ln_h_kernel<<<NS / 8, 256>>>(p_x, ln2_g + l * DMODEL, ln2_b + l * DMODEL, p_h16);
        {
            dim3 grid(MLPD / 128, (NS + 127) / 128);
            tgemm16<1><<<grid, 128, TG16_SMEM>>>(p_h16, p_w1T16 + (size_t)l * DMODEL * MLPD,
                                                 b1 + (size_t)l * MLPD, nullptr,
                                                 p_mlp16, NS, MLPD, DMODEL);
        }
        {
            dim3 grid(DMODEL / 128, (NS + 127) / 128);
            tgemm16<2><<<grid, 128, TG16_SMEM>>>(p_mlp16, p_w2T16 + (size_t)l * MLPD * DMODEL,
                                                 b2 + (size_t)l * DMODEL, p_x,
                                                 p_x, NS, DMODEL, MLPD);
        }
    }

    // 3) head: logits (parallel) + softmax
    {
        dim3 grid((OUTD + 255) / 256, NB);
        logits_kernel<<<grid, 256>>>(p_x, W_head, b_head, p_tokens);
    }
    head_softmax_kernel<<<NB, 256>>>(p_tokens, out);
}

// round 15
// speedup vs baseline: 1.1735x; 1.0132x over previous
#include <cuda_runtime.h>
#include <cuda_bf16.h>
#include <cuda_fp16.h>
#include <math.h>
#include <cstdint>

// ---------------- problem constants ----------------
#define NB     32
#define SEQ    197
#define SEQP   256
#define DMODEL 768
#define NHEAD  12
#define DHEAD  64
#define LAYERS 12
#define MLPD   3072
#define OUTD   1000
#define PPATCH 196
#define IN_DIM 768
#define NS     (NB * SEQ)       // 6304 tokens
#define NP     (NB * PPATCH)    // 6272 patches

// ---------------- device scratch ----------------
__device__ __half g_patches16[NP * IN_DIM];
__device__ float  g_tokens[NP * DMODEL];           // embed output; also logits scratch
__device__ float  g_x[NS * DMODEL];
__device__ __half g_h16[NS * DMODEL];
__device__ __half g_q16[NS * DMODEL];
__device__ __half g_k16[NS * DMODEL];
__device__ __half g_vT16[NB * NHEAD * 64 * SEQP];
__device__ __half g_mlp16[NS * MLPD];
__device__ __half g_wmapT16[DMODEL * IN_DIM];
__device__ __half g_w1T16[LAYERS * MLPD * DMODEL];
__device__ __half g_w2T16[LAYERS * DMODEL * MLPD];
__device__ __half g_wqT16[LAYERS * NHEAD * DHEAD * DHEAD];
__device__ __half g_wkT16[LAYERS * NHEAD * DHEAD * DHEAD];
__device__ __half g_wvT16[LAYERS * NHEAD * DHEAD * DHEAD];

__device__ __forceinline__ int il16(int c)
{
    int r = c & 15;
    int p = ((r & 7) >> 1) * 4 + ((r >> 3) << 1) + (r & 1);
    return (c & ~15) | p;
}
__device__ __forceinline__ int inv16(int c)
{
    int r = c & 15;
    int k = (((r & 3) < 2) ? 0 : 8) + ((r >> 2) << 1) + (r & 1);
    return (c & ~15) | k;
}

__device__ __forceinline__ void mma_f16(float* c, uint32_t a0, uint32_t a1,
                                        uint32_t a2, uint32_t a3,
                                        uint32_t b0, uint32_t b1)
{
    asm volatile(
        "mma.sync.aligned.m16n8k16.row.col.f32.f16.f16.f32 "
        "{%0,%1,%2,%3},{%4,%5,%6,%7},{%8,%9},{%0,%1,%2,%3};"
        : "+f"(c[0]), "+f"(c[1]), "+f"(c[2]), "+f"(c[3])
        : "r"(a0), "r"(a1), "r"(a2), "r"(a3), "r"(b0), "r"(b1));
}

// ---------------- weight prep ----------------
__global__ void __launch_bounds__(256)
cvtT16_kernel(const float* __restrict__ src, __half* __restrict__ dst, int R, int C)
{
    __shared__ float t[32][33];
    size_t zoff = (size_t)blockIdx.z * R * C;
    int bx = blockIdx.x * 32;
    int by = blockIdx.y * 32;
    int tx = threadIdx.x & 31;
    int ty = threadIdx.x >> 5;
    #pragma unroll
    for (int i = 0; i < 32; i += 8)
        t[ty + i][tx] = src[zoff + (size_t)(by + ty + i) * C + bx + tx];
    __syncthreads();
    int kp = il16(by + tx);
    #pragma unroll
    for (int i = 0; i < 32; i += 8)
        dst[zoff + (size_t)(bx + ty + i) * R + kp] = __float2half(t[tx][ty + i]);
}

// ---------------- patchify ----------------
__global__ void __launch_bounds__(256)
patchify_kernel(const float* __restrict__ img)
{
    int idx = blockIdx.x * 256 + threadIdx.x;
    if (idx >= NP * IN_DIM) return;
    int t = idx / IN_DIM;
    int ep = idx - t * IN_DIM;
    int e = inv16(ep);
    int n = t / PPATCH;
    int p = t - n * PPATCH;
    int py = p / 14, px = p - py * 14;
    int c  = e >> 8;
    int r  = e & 255;
    int ph = r >> 4, pw = r & 15;
    g_patches16[idx] = __float2half(
        img[(((size_t)n * 3 + c) * 224 + (py * 16 + ph)) * 224 + px * 16 + pw]);
}

// ---------------- assemble ----------------
__global__ void __launch_bounds__(256)
assemble_kernel(const float* __restrict__ tokens, const float* __restrict__ cls,
                const float* __restrict__ pos)
{
    int idx = blockIdx.x * 256 + threadIdx.x;
    if (idx >= NS * DMODEL) return;
    int t = idx / DMODEL;
    int d = idx - t * DMODEL;
    int n = t / SEQ;
    int s = t - n * SEQ;
    float v = (s == 0) ? cls[d] : tokens[((size_t)(n * PPATCH + s - 1)) * DMODEL + d];
    g_x[idx] = v + pos[s * DMODEL + d];
}

// ---------------- fp16 tensor-core GEMM (proven R13 config) ----------
#define TG16_STAGE 24576
#define TG16_SMEM  (3 * TG16_STAGE)   // 73728 bytes

template<int EPI>
__global__ void __launch_bounds__(128, 2)
tgemm16(const __half* __restrict__ A, const __half* __restrict__ Bt,
        const float* __restrict__ bias, const float* __restrict__ res,
        void* __restrict__ Cv, int M, int N, int K)
{
    extern __shared__ char sm16[];

    const int tid  = threadIdx.x;
    const int wid  = tid >> 5;
    const int lane = tid & 31;
    const int g    = lane >> 2;
    const int tig  = lane & 3;
    const int mw   = wid & 1;
    const int nw   = wid >> 1;
    const int bm   = blockIdx.y * 128;
    const int bn   = blockIdx.x * 128;

    float acc[4][8][4];
    #pragma unroll
    for (int i = 0; i < 4; i++)
        #pragma unroll
        for (int j = 0; j < 8; j++)
            #pragma unroll
            for (int c = 0; c < 4; c++) acc[i][j][c] = 0.f;

    auto As = [&](int buf) { return (__half*)(sm16 + buf * TG16_STAGE); };
    auto Bs = [&](int buf) { return (__half*)(sm16 + buf * TG16_STAGE + 12288); };

    auto load_tile = [&](int kt, int buf) {
        __half* as = As(buf);
        __half* bs = Bs(buf);
        const int kk0 = kt * 32;
        #pragma unroll
        for (int p = 0; p < 4; p++) {
            int idx = p * 128 + tid;
            int row = idx >> 2;
            int ch  = idx & 3;
            const __half* src = A + (size_t)(bm + row) * K + kk0 + ch * 8;
            uint32_t dst = (uint32_t)__cvta_generic_to_shared(as + row * 48 + ch * 8);
            int sz = (bm + row) < M ? 16 : 0;
            asm volatile("cp.async.cg.shared.global [%0], [%1], 16, %2;"
                         :: "r"(dst), "l"(src), "r"(sz) : "memory");
        }
        #pragma unroll
        for (int p = 0; p < 4; p++) {
            int idx = p * 128 + tid;
            int row = idx >> 2;
            int ch  = idx & 3;
            const __half* src = Bt + (size_t)(bn + row) * K + kk0 + ch * 8;
            uint32_t dst = (uint32_t)__cvta_generic_to_shared(bs + row * 48 + ch * 8);
            asm volatile("cp.async.cg.shared.global [%0], [%1], 16;"
                         :: "r"(dst), "l"(src) : "memory");
        }
        asm volatile("cp.async.commit_group;" ::: "memory");
    };

    const int T = K >> 5;
    load_tile(0, 0);
    if (T > 1) load_tile(1, 1);

    int buf = 0;
    for (int kt = 0; kt < T; kt++) {
        if (kt + 1 < T) asm volatile("cp.async.wait_group 1;" ::: "memory");
        else            asm volatile("cp.async.wait_group 0;" ::: "memory");
        __syncthreads();

        if (kt + 2 < T) load_tile(kt + 2, (kt + 2) % 3);

        const __half* as = As(buf);
        const __half* bs = Bs(buf);

        #pragma unroll
        for (int s = 0; s < 2; s++) {
            uint32_t af[4][4];
            #pragma unroll
            for (int mt = 0; mt < 4; mt++) {
                int rb = mw * 64 + mt * 16;
                uint2 lo = *(const uint2*)(as + (rb + g)     * 48 + s * 16 + tig * 4);
                uint2 hi = *(const uint2*)(as + (rb + g + 8) * 48 + s * 16 + tig * 4);
                af[mt][0] = lo.x; af[mt][1] = hi.x; af[mt][2] = lo.y; af[mt][3] = hi.y;
            }
            #pragma unroll
            for (int nt = 0; nt < 8; nt++) {
                int cb = nw * 64 + nt * 8;
                uint2 bv = *(const uint2*)(bs + (cb + g) * 48 + s * 16 + tig * 4);
                #pragma unroll
                for (int mt = 0; mt < 4; mt++)
                    mma_f16(acc[mt][nt], af[mt][0], af[mt][1], af[mt][2], af[mt][3],
                            bv.x, bv.y);
            }
        }
        buf = (buf == 2) ? 0 : buf + 1;
    }

    float* Cf = (float*)Cv;
    __half* Ch = (__half*)Cv;
    #pragma unroll
    for (int mt = 0; mt < 4; mt++) {
        int r0 = bm + mw * 64 + mt * 16 + g;
        #pragma unroll
        for (int nt = 0; nt < 8; nt++) {
            int c0 = bn + nw * 64 + nt * 8 + 2 * tig;
            float b0 = bias[c0], b1 = bias[c0 + 1];
            #pragma unroll
            for (int h = 0; h < 2; h++) {
                int row = r0 + h * 8;
                if (row >= M) continue;
                float v0 = acc[mt][nt][h * 2 + 0] + b0;
                float v1 = acc[mt][nt][h * 2 + 1] + b1;
                if (EPI == 1) {
                    v0 = 0.5f * v0 * (1.f + erff(v0 * 0.70710678118654752f));
                    v1 = 0.5f * v1 * (1.f + erff(v1 * 0.70710678118654752f));
                    int pos = il16(c0);
                    __half2 hv = __floats2half2_rn(v0, v1);
                    *(__half2*)(Ch + (size_t)row * N + pos) = hv;
                } else {
                    if (EPI == 2) {
                        const float2 rr = *(const float2*)(res + (size_t)row * N + c0);
                        v0 += rr.x; v1 += rr.y;
                    }
                    float2 o; o.x = v0; o.y = v1;
                    *(float2*)(Cf + (size_t)row * N + c0) = o;
                }
            }
        }
    }
}

// ---------------- LayerNorm: warp-per-row ----------------
__global__ void __launch_bounds__(256)
ln_h_kernel(const float* __restrict__ x, const float* __restrict__ g,
            const float* __restrict__ b, __half* __restrict__ o)
{
    const int row  = blockIdx.x * 8 + (threadIdx.x >> 5);
    const int lane = threadIdx.x & 31;
    const float* xr = x + (size_t)row * DMODEL;

    float v[24];
    float s = 0.f;
    #pragma unroll
    for (int c = 0; c < 6; c++) {
        float4 t = *(const float4*)(xr + c * 128 + lane * 4);
        v[c * 4 + 0] = t.x; v[c * 4 + 1] = t.y;
        v[c * 4 + 2] = t.z; v[c * 4 + 3] = t.w;
        s += (t.x + t.y) + (t.z + t.w);
    }
    #pragma unroll
    for (int of = 16; of; of >>= 1) s += __shfl_xor_sync(~0u, s, of);
    const float mu = s * (1.f / 768.f);

    float q = 0.f;
    #pragma unroll
    for (int i = 0; i < 24; i++) {
        float d = v[i] - mu;
        v[i] = d;
        q = fmaf(d, d, q);
    }
    #pragma unroll
    for (int of = 16; of; of >>= 1) q += __shfl_xor_sync(~0u, q, of);
    const float inv = rsqrtf(q * (1.f / 768.f) + 1e-5f);

    __half* orow = o + (size_t)row * DMODEL;
    #pragma unroll
    for (int c = 0; c < 6; c++) {
        int d0 = c * 128 + lane * 4;
        const float4 gg = *(const float4*)(g + d0);
        const float4 bb = *(const float4*)(b + d0);
        float o0 = v[c * 4 + 0] * inv * gg.x + bb.x;
        float o1 = v[c * 4 + 1] * inv * gg.y + bb.y;
        float o2 = v[c * 4 + 2] * inv * gg.z + bb.z;
        float o3 = v[c * 4 + 3] * inv * gg.w + bb.w;
        *(__half2*)(orow + il16(d0))     = __floats2half2_rn(o0, o1);
        *(__half2*)(orow + il16(d0 + 2)) = __floats2half2_rn(o2, o3);
    }
}

// ---------------- fused QKV projection: one launch, X loaded once ----------------
// grid ((NS+63)/64, NHEAD), 128 threads. A-fragments preloaded, reused for Q/K/V.
__global__ void __launch_bounds__(128)
qkv16_kernel(const __half* __restrict__ h,
             const __half* __restrict__ Wq, const __half* __restrict__ Wk,
             const __half* __restrict__ Wv,
             const float* __restrict__ bq, const float* __restrict__ bk,
             const float* __restrict__ bv,
             __half* __restrict__ q, __half* __restrict__ k, __half* __restrict__ vT)
{
    __shared__ __half Xs[64][80];
    __shared__ __half Ws[3][64][80];   // 40 KB total static

    const int t0 = blockIdx.x * 64;
    const int hh = blockIdx.y;
    const size_t woff = (size_t)hh * 64 * 64;
    const __half* Wz[3] = { Wq + woff, Wk + woff, Wv + woff };
    const float*  Bz[3] = { bq + hh * 64, bk + hh * 64, bv + hh * 64 };

    const int tid  = threadIdx.x;
    const int wid  = tid >> 5;
    const int lane = tid & 31;
    const int g    = lane >> 2;
    const int tig  = lane & 3;
    const int rb   = wid * 16;

    #pragma unroll
    for (int it = 0; it < 4; it++) {
        int idx = it * 128 + tid;
        int row = idx >> 3;
        int ch  = idx & 7;
        int tok = t0 + row;
        uint4 xv = make_uint4(0u, 0u, 0u, 0u);
        if (tok < NS) xv = *(const uint4*)(h + (size_t)tok * DMODEL + hh * 64 + ch * 8);
        *(uint4*)&Xs[row][ch * 8] = xv;
        #pragma unroll
        for (int z = 0; z < 3; z++)
            *(uint4*)&Ws[z][row][ch * 8] = *(const uint4*)(Wz[z] + row * 64 + ch * 8);
    }
    __syncthreads();

    // preload A-fragments once, reuse across the 3 output projections
    uint32_t axf[4][4];
    #pragma unroll
    for (int s = 0; s < 4; s++) {
        uint2 lo = *(const uint2*)&Xs[rb + g]    [s * 16 + tig * 4];
        uint2 hi = *(const uint2*)&Xs[rb + g + 8][s * 16 + tig * 4];
        axf[s][0] = lo.x; axf[s][1] = hi.x; axf[s][2] = lo.y; axf[s][3] = hi.y;
    }

    #pragma unroll
    for (int z = 0; z < 3; z++) {
        float acc[8][4];
        #pragma unroll
        for (int nt = 0; nt < 8; nt++)
            #pragma unroll
            for (int c = 0; c < 4; c++) acc[nt][c] = 0.f;

        #pragma unroll
        for (int s = 0; s < 4; s++)
            #pragma unroll
            for (int nt = 0; nt < 8; nt++) {
                uint2 bv = *(const uint2*)&Ws[z][nt * 8 + g][s * 16 + tig * 4];
                mma_f16(acc[nt], axf[s][0], axf[s][1], axf[s][2], axf[s][3],
                        bv.x, bv.y);
            }

        const float* bb = Bz[z];
        __half* out = (z == 0) ? q : k;
        #pragma unroll
        for (int nt = 0; nt < 8; nt++) {
            int c0 = nt * 8 + 2 * tig;
            float b0 = bb[c0], b1 = bb[c0 + 1];
            #pragma unroll
            for (int hlf = 0; hlf < 2; hlf++) {
                int tok = t0 + rb + g + hlf * 8;
                if (tok >= NS) continue;
                float v0 = acc[nt][hlf * 2 + 0] + b0;
                float v1 = acc[nt][hlf * 2 + 1] + b1;
                if (z < 2) {
                    __half2 hv = __floats2half2_rn(v0, v1);
                    *(__half2*)(out + (size_t)tok * DMODEL + hh * 64 + il16(c0)) = hv;
                } else {
                    int n  = tok / SEQ;
                    int s_ = tok - n * SEQ;
                    int b  = n * NHEAD + hh;
                    int kp = il16(s_);
                    vT[((size_t)b * 64 + c0)     * SEQP + kp] = __float2half(v0);
                    vT[((size_t)b * 64 + c0 + 1) * SEQP + kp] = __float2half(v1);
                }
            }
        }
    }
}

// ---------------- fused flash attention, cp.async double-buffered K/V ----------------
#define ATTN_SMEM (6 * 64 * 80 * 2)   // 61440 bytes dynamic

__global__ void __launch_bounds__(128)
attn16_kernel(const __half* __restrict__ q, const __half* __restrict__ k,
              const __half* __restrict__ vT, float* __restrict__ x)
{
    extern __shared__ __half asmem[];
    __half (*Qs)[80] = (__half(*)[80])(asmem);
    __half (*Ps)[80] = (__half(*)[80])(asmem + 64 * 80);
    // Ks[buf], Vs[buf]
    auto Ks = [&](int bufi) { return (__half(*)[80])(asmem + (2 + bufi) * 64 * 80); };
    auto Vs = [&](int bufi) { return (__half(*)[80])(asmem + (4 + bufi) * 64 * 80); };

    const int q0 = blockIdx.x * 64;
    const int b  = blockIdx.y;
    const int n  = b / NHEAD, hh = b - n * NHEAD;
    const int tid  = threadIdx.x;
    const int wid  = tid >> 5;
    const int lane = tid & 31;
    const int g    = lane >> 2;
    const int tig  = lane & 3;
    const int rb   = wid * 16;

    // async K/V tile loader
    auto load_kv = [&](int kt, int bufi) {
        __half (*ks)[80] = Ks(bufi);
        __half (*vs)[80] = Vs(bufi);
        const int k0 = kt * 64;
        #pragma unroll
        for (int it = 0; it < 4; it++) {
            int idx = it * 128 + tid;
            int row = idx >> 3;
            int ch  = idx & 7;
            int ktok = k0 + row;
            const __half* srcK = k + ((size_t)(n * SEQ + ktok)) * DMODEL + hh * 64 + ch * 8;
            uint32_t dstK = (uint32_t)__cvta_generic_to_shared(&ks[row][ch * 8]);
            int sz = (ktok < SEQ) ? 16 : 0;
            asm volatile("cp.async.cg.shared.global [%0], [%1], 16, %2;"
                         :: "r"(dstK), "l"(srcK), "r"(sz) : "memory");
            const __half* srcV = vT + ((size_t)b * 64 + row) * SEQP + k0 + ch * 8;
            uint32_t dstV = (uint32_t)__cvta_generic_to_shared(&vs[row][ch * 8]);
            asm volatile("cp.async.cg.shared.global [%0], [%1], 16;"
                         :: "r"(dstV), "l"(srcV) : "memory");
        }
        asm volatile("cp.async.commit_group;" ::: "memory");
    };

    // load Q tile (blocking) + prefetch first K/V tile
    load_kv(0, 0);
    #pragma unroll
    for (int it = 0; it < 4; it++) {
        int idx = it * 128 + tid;
        int row = idx >> 3;
        int ch  = idx & 7;
        int qt = q0 + row;
        uint4 qv = make_uint4(0u, 0u, 0u, 0u);
        if (qt < SEQ) qv = *(const uint4*)(q + (size_t)(n * SEQ + qt) * DMODEL + hh * 64 + ch * 8);
        *(uint4*)&Qs[row][ch * 8] = qv;
    }

    float m_run[2] = {-1e30f, -1e30f};
    float l_run[2] = {0.f, 0.f};
    float acc_o[8][4];
    #pragma unroll
    for (int nt = 0; nt < 8; nt++)
        #pragma unroll
        for (int c = 0; c < 4; c++) acc_o[nt][c] = 0.f;

    for (int kt = 0; kt < 4; kt++) {
        const int bufi = kt & 1;
        asm volatile("cp.async.wait_group 0;" ::: "memory");
        __syncthreads();

        if (kt + 1 < 4) load_kv(kt + 1, bufi ^ 1);   // overlap with compute below

        __half (*KsB)[80] = Ks(bufi);
        __half (*VsB)[80] = Vs(bufi);
        const int k0 = kt * 64;

        float s[8][4];
        #pragma unroll
        for (int nt = 0; nt < 8; nt++)
            #pragma unroll
            for (int c = 0; c < 4; c++) s[nt][c] = 0.f;

        #pragma unroll
        for (int ss = 0; ss < 4; ss++) {
            uint2 lo = *(const uint2*)&Qs[rb + g]    [ss * 16 + tig * 4];
            uint2 hi = *(const uint2*)&Qs[rb + g + 8][ss * 16 + tig * 4];
            #pragma unroll
            for (int nt = 0; nt < 8; nt++) {
                uint2 bv = *(const uint2*)&KsB[nt * 8 + g][ss * 16 + tig * 4];
                mma_f16(s[nt], lo.x, hi.x, lo.y, hi.y, bv.x, bv.y);
            }
        }

        // scale + key mask (overwrites garbage in padded keys)
        #pragma unroll
        for (int nt = 0; nt < 8; nt++) {
            int c0 = k0 + nt * 8 + 2 * tig;
            s[nt][0] = (c0     < SEQ) ? s[nt][0] * 0.125f : -1e30f;
            s[nt][1] = (c0 + 1 < SEQ) ? s[nt][1] * 0.125f : -1e30f;
            s[nt][2] = (c0     < SEQ) ? s[nt][2] * 0.125f : -1e30f;
            s[nt][3] = (c0 + 1 < SEQ) ? s[nt][3] * 0.125f : -1e30f;
        }

        // online softmax (row0 = rb+g: c0,c1; row1 = rb+g+8: c2,c3)
        #pragma unroll
        for (int r = 0; r < 2; r++) {
            float mt_ = -1e30f;
            #pragma unroll
            for (int nt = 0; nt < 8; nt++)
                mt_ = fmaxf(mt_, fmaxf(s[nt][2 * r], s[nt][2 * r + 1]));
            mt_ = fmaxf(mt_, __shfl_xor_sync(~0u, mt_, 1));
            mt_ = fmaxf(mt_, __shfl_xor_sync(~0u, mt_, 2));
            float mnew = fmaxf(m_run[r], mt_);
            float sc = expf(m_run[r] - mnew);
            float rs = 0.f;
            #pragma unroll
            for (int nt = 0; nt < 8; nt++) {
                float p0 = expf(s[nt][2 * r]     - mnew);
                float p1 = expf(s[nt][2 * r + 1] - mnew);
                s[nt][2 * r] = p0; s[nt][2 * r + 1] = p1;
                rs += p0 + p1;
            }
            rs += __shfl_xor_sync(~0u, rs, 1);
            rs += __shfl_xor_sync(~0u, rs, 2);
            l_run[r] = l_run[r] * sc + rs;
            #pragma unroll
            for (int nt = 0; nt < 8; nt++) {
                acc_o[nt][2 * r]     *= sc;
                acc_o[nt][2 * r + 1] *= sc;
            }
            m_run[r] = mnew;
        }

        // stage P (fp16, key-interleaved); warp-local rows
        #pragma unroll
        for (int nt = 0; nt < 8; nt++) {
            int pc = il16(nt * 8 + 2 * tig);
            *(__half2*)&Ps[rb + g]    [pc] = __floats2half2_rn(s[nt][0], s[nt][1]);
            *(__half2*)&Ps[rb + g + 8][pc] = __floats2half2_rn(s[nt][2], s[nt][3]);
        }
        __syncwarp();

        // O += P @ V
        #pragma unroll
        for (int ss = 0; ss < 4; ss++) {
            uint2 lo = *(const uint2*)&Ps[rb + g]    [ss * 16 + tig * 4];
            uint2 hi = *(const uint2*)&Ps[rb + g + 8][ss * 16 + tig * 4];
            #pragma unroll
            for (int nt = 0; nt < 8; nt++) {
                uint2 bv = *(const uint2*)&VsB[nt * 8 + g][ss * 16 + tig * 4];
                mma_f16(acc_o[nt], lo.x, hi.x, lo.y, hi.y, bv.x, bv.y);
            }
        }
        __syncthreads();   // all reads of this buffer done before it can be refilled
    }

    #pragma unroll
    for (int r = 0; r < 2; r++) {
        int row = q0 + rb + g + r * 8;
        if (row >= SEQ) continue;
        float inv = 1.f / l_run[r];
        #pragma unroll
        for (int nt = 0; nt < 8; nt++) {
            int col = hh * 64 + nt * 8 + 2 * tig;
            float* px = x + (size_t)(n * SEQ + row) * DMODEL + col;
            float2 old = *(float2*)px;
            old.x += acc_o[nt][2 * r]     * inv;
            old.y += acc_o[nt][2 * r + 1] * inv;
            *(float2*)px = old;
        }
    }
}

// ---------------- head: parallel logits ----------------
__global__ void __launch_bounds__(256)
logits_kernel(const float* __restrict__ x, const float* __restrict__ Wh,
              const float* __restrict__ bh, float* __restrict__ lg)
{
    __shared__ float xs[DMODEL];
    int n  = blockIdx.y;
    int o  = blockIdx.x * 256 + threadIdx.x;
    for (int i = threadIdx.x; i < DMODEL; i += 256)
        xs[i] = x[(size_t)n * SEQ * DMODEL + i];
    __syncthreads();
    if (o >= OUTD) return;
    float a = bh[o];
    #pragma unroll 4
    for (int kk = 0; kk < DMODEL; kk++)
        a = fmaf(xs[kk], Wh[(size_t)kk * OUTD + o], a);
    lg[n * OUTD + o] = a;
}

// ---------------- head: per-image softmax ----------------
__global__ void __launch_bounds__(256)
head_softmax_kernel(const float* __restrict__ lg, float* __restrict__ out)
{
    __shared__ float red[256];
    int n = blockIdx.x, tid = threadIdx.x;
    const float* l = lg + n * OUTD;
    float m = -1e30f;
    for (int o = tid; o < OUTD; o += 256) m = fmaxf(m, l[o]);
    red[tid] = m; __syncthreads();
    for (int s = 128; s; s >>= 1) { if (tid < s) red[tid] = fmaxf(red[tid], red[tid + s]); __syncthreads(); }
    float mx = red[0]; __syncthreads();
    float sm = 0.f;
    for (int o = tid; o < OUTD; o += 256) sm += expf(l[o] - mx);
    red[tid] = sm; __syncthreads();
    for (int s = 128; s; s >>= 1) { if (tid < s) red[tid] += red[tid + s]; __syncthreads(); }
    float inv = 1.f / red[0];
    __syncthreads();
    for (int o = tid; o < OUTD; o += 256)
        out[(size_t)n * OUTD + o] = expf(l[o] - mx) * inv;
}

// ---------------- host orchestration ----------------
extern "C" void kernel_launch(void* const* d_in, const int* in_sizes, int n_in,
                              void* d_out, int out_size)
{
    const float* images   = (const float*)d_in[0];
    const float* W_map    = (const float*)d_in[1];
    const float* b_map    = (const float*)d_in[2];
    const float* cls      = (const float*)d_in[3];
    const float* pos      = (const float*)d_in[4];
    const float* ln1_g    = (const float*)d_in[5];
    const float* ln1_b    = (const float*)d_in[6];
    const float* Wq       = (const float*)d_in[7];
    const float* bq       = (const float*)d_in[8];
    const float* Wk       = (const float*)d_in[9];
    const float* bk       = (const float*)d_in[10];
    const float* Wv       = (const float*)d_in[11];
    const float* bv       = (const float*)d_in[12];
    const float* ln2_g    = (const float*)d_in[13];
    const float* ln2_b    = (const float*)d_in[14];
    const float* W1       = (const float*)d_in[15];
    const float* b1       = (const float*)d_in[16];
    const float* W2       = (const float*)d_in[17];
    const float* b2       = (const float*)d_in[18];
    const float* W_head   = (const float*)d_in[19];
    const float* b_head   = (const float*)d_in[20];
    float* out = (float*)d_out;

    __half *p_patches16, *p_h16, *p_mlp16, *p_q16, *p_k16, *p_vT16;
    __half *p_wmapT16, *p_w1T16, *p_w2T16, *p_wqT16, *p_wkT16, *p_wvT16;
    float *p_tokens, *p_x;
    cudaGetSymbolAddress((void**)&p_patches16, g_patches16);
    cudaGetSymbolAddress((void**)&p_tokens, g_tokens);
    cudaGetSymbolAddress((void**)&p_x, g_x);
    cudaGetSymbolAddress((void**)&p_h16, g_h16);
    cudaGetSymbolAddress((void**)&p_q16, g_q16);
    cudaGetSymbolAddress((void**)&p_k16, g_k16);
    cudaGetSymbolAddress((void**)&p_vT16, g_vT16);
    cudaGetSymbolAddress((void**)&p_mlp16, g_mlp16);
    cudaGetSymbolAddress((void**)&p_wmapT16, g_wmapT16);
    cudaGetSymbolAddress((void**)&p_w1T16, g_w1T16);
    cudaGetSymbolAddress((void**)&p_w2T16, g_w2T16);
    cudaGetSymbolAddress((void**)&p_wqT16, g_wqT16);
    cudaGetSymbolAddress((void**)&p_wkT16, g_wkT16);
    cudaGetSymbolAddress((void**)&p_wvT16, g_wvT16);

    cudaFuncSetAttribute(tgemm16<0>, cudaFuncAttributeMaxDynamicSharedMemorySize, TG16_SMEM);
    cudaFuncSetAttribute(tgemm16<1>, cudaFuncAttributeMaxDynamicSharedMemorySize, TG16_SMEM);
    cudaFuncSetAttribute(tgemm16<2>, cudaFuncAttributeMaxDynamicSharedMemorySize, TG16_SMEM);
    cudaFuncSetAttribute(attn16_kernel, cudaFuncAttributeMaxDynamicSharedMemorySize, ATTN_SMEM);

    // 0) weight prep
    {
        dim3 gmap(DMODEL / 32, IN_DIM / 32, 1);
        cvtT16_kernel<<<gmap, 256>>>(W_map, p_wmapT16, IN_DIM, DMODEL);
        dim3 g1(MLPD / 32, DMODEL / 32, LAYERS);
        cvtT16_kernel<<<g1, 256>>>(W1, p_w1T16, DMODEL, MLPD);
        dim3 g2(DMODEL / 32, MLPD / 32, LAYERS);
        cvtT16_kernel<<<g2, 256>>>(W2, p_w2T16, MLPD, DMODEL);
        dim3 gq(2, 2, LAYERS * NHEAD);
        cvtT16_kernel<<<gq, 256>>>(Wq, p_wqT16, DHEAD, DHEAD);
        cvtT16_kernel<<<gq, 256>>>(Wk, p_wkT16, DHEAD, DHEAD);
        cvtT16_kernel<<<gq, 256>>>(Wv, p_wvT16, DHEAD, DHEAD);
    }

    // 1) patchify + embed + assemble
    patchify_kernel<<<(NP * IN_DIM) / 256, 256>>>(images);
    {
        dim3 grid(DMODEL / 128, NP / 128);
        tgemm16<0><<<grid, 128, TG16_SMEM>>>(p_patches16, p_wmapT16, b_map, nullptr,
                                             p_tokens, NP, DMODEL, IN_DIM);
    }
    assemble_kernel<<<(NS * DMODEL) / 256, 256>>>(p_tokens, cls, pos);

    // 2) transformer blocks
    for (int l = 0; l < LAYERS; l++) {
        ln_h_kernel<<<NS / 8, 256>>>(p_x, ln1_g + l * DMODEL, ln1_b + l * DMODEL, p_h16);

        {
            dim3 grid((NS + 63) / 64, NHEAD);
            qkv16_kernel<<<grid, 128>>>(p_h16,
                p_wqT16 + (size_t)l * NHEAD * DHEAD * DHEAD,
                p_wkT16 + (size_t)l * NHEAD * DHEAD * DHEAD,
                p_wvT16 + (size_t)l * NHEAD * DHEAD * DHEAD,
                bq + (size_t)l * NHEAD * DHEAD,
                bk + (size_t)l * NHEAD * DHEAD,
                bv + (size_t)l * NHEAD * DHEAD,
                p_q16, p_k16, p_vT16);
        }
        {
            dim3 grid((SEQ + 63) / 64, NB * NHEAD);
            attn16_kernel<<<grid, 128, ATTN_SMEM>>>(p_q16, p_k16, p_vT16, p_x);
        }

        ln_h_kernel<<<NS / 8, 256>>>(p_x, ln2_g + l * DMODEL, ln2_b + l * DMODEL, p_h16);
        {
            dim3 grid(MLPD / 128, (NS + 127) / 128);
            tgemm16<1><<<grid, 128, TG16_SMEM>>>(p_h16, p_w1T16 + (size_t)l * DMODEL * MLPD,
                                                 b1 + (size_t)l * MLPD, nullptr,
                                                 p_mlp16, NS, MLPD, DMODEL);
        }
        {
            dim3 grid(DMODEL / 128, (NS + 127) / 128);
            tgemm16<2><<<grid, 128, TG16_SMEM>>>(p_mlp16, p_w2T16 + (size_t)l * MLPD * DMODEL,
                                                 b2 + (size_t)l * DMODEL, p_x,
                                                 p_x, NS, DMODEL, MLPD);
        }
    }

    // 3) head: logits (parallel) + softmax
    {
        dim3 grid((OUTD + 255) / 256, NB);
        logits_kernel<<<grid, 256>>>(p_x, W_head, b_head, p_tokens);
    }
    head_softmax_kernel<<<NB, 256>>>(p_tokens, out);
}